// round 6
// baseline (speedup 1.0000x reference)
#include <cuda_runtime.h>
#include <math.h>

#define BS    2048
#define C1    22
#define WIN   438
#define C2    20
#define W2L   439
#define NIN   20
#define NOUT  18
#define NEP   3
#define KW    12
#define NMATQKV (BS*NEP*3)      // 18432 matrices (Q,K,V per (b,m))
#define VECLEN  513             // 3 * 171
#define LN_RECT (-9.2103403719761836f)  // log(1e-4)

// ---------------- scratch (static device globals; no cudaMalloc allowed) ----
__device__ float g_h1[BS*C1*WIN];          // conv1 raw output
__device__ float g_h2[BS*C2*W2L];          // conv2 raw output
__device__ float g_spd[(size_t)NMATQKV*NOUT*NOUT];  // Q/K/V then overwritten by logm
__device__ float g_vec[(size_t)BS*VECLEN];
__device__ float g_red[2*C1 + 2*C2];       // s1[22] q1[22] s2[20] q2[20]
__device__ float g_aff[2*C1 + 2*C2];       // a1[22] c1[22] a2[20] c2[20]

// ---------------------------------------------------------------- zero stats
__global__ void k_zero() {
    int t = threadIdx.x;
    if (t < 2*C1 + 2*C2) g_red[t] = 0.f;
}

// ------------------------------------------------------- conv1 + bn1 stats
__global__ void k_conv1(const float* __restrict__ x,
                        const float* __restrict__ W1,
                        const float* __restrict__ b1) {
    __shared__ float w1s[C1*C1];
    __shared__ float sS[C1], sQ[C1];
    int tid = threadIdx.x;
    for (int t = tid; t < C1*C1; t += blockDim.x) w1s[t] = W1[t];  // W1[o,0,h,0]
    if (tid < C1) { sS[tid] = 0.f; sQ[tid] = 0.f; }
    __syncthreads();

    int g = blockIdx.x * blockDim.x + tid;
    bool valid = (g < BS*WIN);
    int b = g / WIN, w = g % WIN;
    float xv[C1];
    if (valid) {
        #pragma unroll
        for (int h = 0; h < C1; h++) xv[h] = x[((size_t)b*C1 + h)*WIN + w];
    }
    for (int o = 0; o < C1; o++) {
        float acc = 0.f;
        if (valid) {
            acc = b1[o];
            #pragma unroll
            for (int h = 0; h < C1; h++) acc += xv[h] * w1s[o*C1 + h];
            g_h1[((size_t)b*C1 + o)*WIN + w] = acc;
        }
        float s = acc, q = acc*acc;
        #pragma unroll
        for (int d = 16; d; d >>= 1) {
            s += __shfl_xor_sync(0xffffffffu, s, d);
            q += __shfl_xor_sync(0xffffffffu, q, d);
        }
        if ((tid & 31) == 0) { atomicAdd(&sS[o], s); atomicAdd(&sQ[o], q); }
    }
    __syncthreads();
    if (tid < C1) {
        atomicAdd(&g_red[tid], sS[tid]);
        atomicAdd(&g_red[C1 + tid], sQ[tid]);
    }
}

__global__ void k_fin1(const float* __restrict__ g1, const float* __restrict__ be1) {
    int c = threadIdx.x;
    if (c >= C1) return;
    float cnt  = (float)((size_t)BS*WIN);
    float mean = g_red[c] / cnt;
    float var  = g_red[C1 + c] / cnt - mean*mean;
    float a = g1[c] * rsqrtf(var + 1e-5f);
    g_aff[c]      = a;
    g_aff[C1 + c] = be1[c] - mean*a;
}

// ------------------------------------------------------- conv2 + bn2 stats
// block: (w-tile of 256, batch). thread: 4 wl x 5 oc outputs.
#define CTILE 256
#define TPAD  267   // 256 + 11, odd stride (conflict-free)
__global__ __launch_bounds__(256) void k_conv2(const float* __restrict__ W2,
                                               const float* __restrict__ b2) {
    __shared__ float tile[C1*TPAD];     // 5874 floats
    __shared__ float w2s[C2*C1*KW];     // 5280 floats
    __shared__ float sS[C2], sQ[C2];
    int tid = threadIdx.x;
    int b  = blockIdx.y;
    int w0 = blockIdx.x * CTILE;

    for (int t = tid; t < C2*C1*KW; t += 256) w2s[t] = W2[t];
    if (tid < C2) { sS[tid] = 0.f; sQ[tid] = 0.f; }
    for (int t = tid; t < C1*TPAD; t += 256) {
        int i = t / TPAD, dw = t % TPAD;
        int gw = w0 - 6 + dw;
        float v = 0.f;
        if (gw >= 0 && gw < WIN)
            v = g_aff[i] * g_h1[((size_t)b*C1 + i)*WIN + gw] + g_aff[C1 + i];
        tile[t] = v;
    }
    __syncthreads();

    int o_grp = tid >> 6;        // 0..3 (warp-uniform)
    int widx  = tid & 63;
    int wl0   = widx * 4;

    float acc[20];
    #pragma unroll
    for (int oi = 0; oi < 5; oi++) {
        float bb = b2[o_grp*5 + oi];
        #pragma unroll
        for (int wj = 0; wj < 4; wj++) acc[oi*4 + wj] = bb;
    }
    for (int i = 0; i < C1; i++) {
        float tv[15];
        #pragma unroll
        for (int u = 0; u < 15; u++) tv[u] = tile[i*TPAD + wl0 + u];
        #pragma unroll
        for (int oi = 0; oi < 5; oi++) {
            int o = o_grp*5 + oi;
            #pragma unroll
            for (int k = 0; k < KW; k++) {
                float wv = w2s[(o*C1 + i)*KW + k];
                #pragma unroll
                for (int wj = 0; wj < 4; wj++) acc[oi*4 + wj] += tv[wj + k] * wv;
            }
        }
    }
    for (int oi = 0; oi < 5; oi++) {
        int o = o_grp*5 + oi;
        float s = 0.f, q = 0.f;
        #pragma unroll
        for (int wj = 0; wj < 4; wj++) {
            int w = w0 + wl0 + wj;
            if (w < W2L) {
                float v = acc[oi*4 + wj];
                g_h2[((size_t)b*C2 + o)*W2L + w] = v;
                s += v; q += v*v;
            }
        }
        #pragma unroll
        for (int d = 16; d; d >>= 1) {
            s += __shfl_xor_sync(0xffffffffu, s, d);
            q += __shfl_xor_sync(0xffffffffu, q, d);
        }
        if ((tid & 31) == 0) { atomicAdd(&sS[o], s); atomicAdd(&sQ[o], q); }
    }
    __syncthreads();
    if (tid < C2) {
        atomicAdd(&g_red[2*C1 + tid], sS[tid]);
        atomicAdd(&g_red[2*C1 + C2 + tid], sQ[tid]);
    }
}

__global__ void k_fin2(const float* __restrict__ g2, const float* __restrict__ be2) {
    int c = threadIdx.x;
    if (c >= C2) return;
    float cnt  = (float)((size_t)BS*W2L);
    float mean = g_red[2*C1 + c] / cnt;
    float var  = g_red[2*C1 + C2 + c] / cnt - mean*mean;
    float a = g2[c] * rsqrtf(var + 1e-5f);
    g_aff[2*C1 + c]      = a;
    g_aff[2*C1 + C2 + c] = be2[c] - mean*a;
}

// ----------------------------------------- covariance + Q/K/V congruence
#define SP 149   // row stride for sig (gcd(149,32)=1)
__global__ __launch_bounds__(192) void k_cov(const float* __restrict__ Wq,
                                             const float* __restrict__ Wk,
                                             const float* __restrict__ Wv) {
    __shared__ float sig[C2*SP];
    __shared__ float Cm[C2*C2];
    __shared__ float T[C2*NOUT];
    __shared__ float Ws[C2*NOUT];
    __shared__ float mean_s[C2];
    __shared__ float trs;
    const int offs[NEP] = {0, 147, 293};
    const int Ls[NEP]   = {147, 146, 146};
    int m = blockIdx.x, b = blockIdx.y;
    int off = offs[m], L = Ls[m];
    int tid = threadIdx.x;
    int warp = tid >> 5, lane = tid & 31;

    for (int t = tid; t < C2*L; t += 192) {
        int c = t / L, l = t % L;
        sig[c*SP + l] = g_aff[2*C1 + c] * g_h2[((size_t)b*C2 + c)*W2L + off + l]
                      + g_aff[2*C1 + C2 + c];
    }
    __syncthreads();
    for (int r = warp; r < C2; r += 6) {
        float s = 0.f;
        for (int l = lane; l < L; l += 32) s += sig[r*SP + l];
        #pragma unroll
        for (int d = 16; d; d >>= 1) s += __shfl_xor_sync(0xffffffffu, s, d);
        if (!lane) mean_s[r] = s / (float)L;
    }
    __syncthreads();
    for (int t = tid; t < C2*L; t += 192) sig[(t/L)*SP + (t%L)] -= mean_s[t/L];
    __syncthreads();
    for (int t = tid; t < 210; t += 192) {
        int p = 0, rem = t;
        while (rem >= C2 - p) { rem -= C2 - p; p++; }
        int q = p + rem;
        float s = 0.f;
        for (int l = 0; l < L; l++) s += sig[p*SP + l] * sig[q*SP + l];
        Cm[p*C2 + q] = s;
        Cm[q*C2 + p] = s;
    }
    __syncthreads();
    if (tid == 0) {
        float tr = 0.f;
        for (int i = 0; i < C2; i++) tr += Cm[i*C2 + i];
        trs = 1.f / tr;                    // (L-1) cancels in trace-normalization
    }
    __syncthreads();
    for (int t = tid; t < C2*C2; t += 192) {
        float v = Cm[t] * trs;
        if (t / C2 == t % C2) v += 1e-5f;
        Cm[t] = v;
    }
    __syncthreads();
    const float* Wp[3] = {Wq, Wk, Wv};
    for (int which = 0; which < 3; which++) {
        for (int t = tid; t < C2*NOUT; t += 192) Ws[t] = Wp[which][t];
        __syncthreads();
        for (int t = tid; t < C2*NOUT; t += 192) {
            int p = t / NOUT, j = t % NOUT;
            float s = 0.f;
            #pragma unroll
            for (int q = 0; q < C2; q++) s += Cm[p*C2 + q] * Ws[q*NOUT + j];
            T[t] = s;
        }
        __syncthreads();
        float* dst = &g_spd[((size_t)(b*NEP + m)*3 + which)*NOUT*NOUT];
        for (int t = tid; t < NOUT*NOUT; t += 192) {
            int i = t / NOUT, j = t % NOUT;
            float s = 0.f;
            #pragma unroll
            for (int p = 0; p < C2; p++) s += Ws[p*NOUT + i] * T[p*NOUT + j];
            dst[t] = s;
        }
        __syncthreads();
    }
}

// ------------------------------ warp-level parallel-round Jacobi (18x18)
// A, Vv: 18x18 in smem with row stride 19. cs/sn: 9 floats, pr/qr: 9 ints.
__device__ __forceinline__ void warp_jacobi18(float* A, float* Vv,
                                              float* cs, float* sn,
                                              int* pr, int* qr,
                                              int lane, int nsweep) {
    for (int e = lane; e < 324; e += 32)
        Vv[(e/18)*19 + (e%18)] = (e/18 == e%18) ? 1.f : 0.f;
    __syncwarp();
    for (int sw = 0; sw < nsweep; sw++) {
        for (int r = 0; r < 17; r++) {
            if (lane < 9) {
                int a  = (lane == 0) ? 0 : (1 + ((lane - 1 + r) % 17));
                int jj = 17 - lane;
                int bb = 1 + ((jj - 1 + r) % 17);
                int p = a < bb ? a : bb;
                int q = a < bb ? bb : a;
                float app = A[p*19 + p], aqq = A[q*19 + q], apq = A[p*19 + q];
                float c = 1.f, s = 0.f;
                if (fabsf(apq) > 1e-36f) {
                    float tau = (aqq - app) / (2.f * apq);
                    float tt  = 1.f / (fabsf(tau) + sqrtf(1.f + tau*tau));
                    if (tau < 0.f) tt = -tt;
                    c = rsqrtf(1.f + tt*tt);
                    s = tt * c;
                }
                pr[lane] = p; qr[lane] = q; cs[lane] = c; sn[lane] = s;
            }
            __syncwarp();
            // phase 1: row rotations on A (J^T A) + column rotations on V (V J)
            for (int t = lane; t < 162; t += 32) {
                int pi = t / 18, k = t % 18;
                int p = pr[pi], q = qr[pi];
                float c = cs[pi], s = sn[pi];
                float apk = A[p*19 + k], aqk = A[q*19 + k];
                A[p*19 + k] = c*apk - s*aqk;
                A[q*19 + k] = s*apk + c*aqk;
                float vkp = Vv[k*19 + p], vkq = Vv[k*19 + q];
                Vv[k*19 + p] = c*vkp - s*vkq;
                Vv[k*19 + q] = s*vkp + c*vkq;
            }
            __syncwarp();
            // phase 2: column rotations on A  ((J^T A) J)
            for (int t = lane; t < 162; t += 32) {
                int pi = t / 18, k = t % 18;
                int p = pr[pi], q = qr[pi];
                float c = cs[pi], s = sn[pi];
                float akp = A[k*19 + p], akq = A[k*19 + q];
                A[k*19 + p] = c*akp - s*akq;
                A[k*19 + q] = s*akp + c*akq;
            }
            __syncwarp();
        }
    }
}

// --------------------------------------- eigh + log for all Q/K/V matrices
#define EW 768
__global__ __launch_bounds__(256) void k_eighlog() {
    __shared__ float sm[8*EW];
    int wid = threadIdx.x >> 5, lane = threadIdx.x & 31;
    size_t mat = (size_t)blockIdx.x * 8 + wid;
    float* A  = &sm[wid*EW];
    float* Vv = A + 342;
    float* ev = Vv + 342;
    float* cs = ev + 18;
    float* sn = cs + 9;
    int*   pr = (int*)(sn + 9);
    int*   qr = pr + 9;
    float* src = &g_spd[mat * 324];
    for (int e = lane; e < 324; e += 32) A[(e/18)*19 + (e%18)] = src[e];
    __syncwarp();
    warp_jacobi18(A, Vv, cs, sn, pr, qr, lane, 8);
    for (int k = lane; k < 18; k += 32) ev[k] = logf(fmaxf(A[k*19 + k], 1e-38f));
    __syncwarp();
    // pre-scale: A[i][k] = Vv[i][k] * ev[k]  (A no longer needed; halves FMULs below)
    for (int e = lane; e < 324; e += 32) {
        int i = e / 18, k = e % 18;
        A[i*19 + k] = Vv[i*19 + k] * ev[k];
    }
    __syncwarp();
    for (int e = lane; e < 324; e += 32) {
        int i = e / 18, j = e % 18;
        float s = 0.f;
        #pragma unroll
        for (int k = 0; k < 18; k++) s += A[i*19 + k] * Vv[j*19 + k];
        src[e] = s;  // overwrite with log-matrix
    }
}

// ------------- attention: energies, softmax, mix, eigh(mixed), triu-vec
// key identity: log(spd_rect(spd_exp(M), eps)) = U diag(max(s, log(eps))) U^T
__global__ __launch_bounds__(288) void k_attn() {
    __shared__ float sLQ[3*324], sLK[3*324], sLV[3*324], sMix[3*324];
    __shared__ float sE[9], sP[9];
    __shared__ float eigsm[3*EW];
    int b = blockIdx.x, tid = threadIdx.x;
    int warp = tid >> 5, lane = tid & 31;
    size_t base = (size_t)b * 9 * 324;
    for (int t = tid; t < 3*324; t += 288) {
        int mm = t / 324, e = t % 324;
        sLQ[t] = g_spd[base + (mm*3 + 0)*324 + e];
        sLK[t] = g_spd[base + (mm*3 + 1)*324 + e];
        sLV[t] = g_spd[base + (mm*3 + 2)*324 + e];
    }
    __syncthreads();
    {   // 9 warps -> 9 (i,j) energy pairs
        int i = warp / 3, j = warp % 3;
        float s = 0.f;
        for (int e = lane; e < 324; e += 32) {
            float d = sLQ[i*324 + e] - sLK[j*324 + e];
            s += d*d;
        }
        #pragma unroll
        for (int d = 16; d; d >>= 1) s += __shfl_xor_sync(0xffffffffu, s, d);
        if (!lane) sE[i*3 + j] = s;
    }
    __syncthreads();
    if (tid < 3) {
        float sc[3]; float mx = -1e30f;
        #pragma unroll
        for (int j = 0; j < 3; j++) {
            sc[j] = 1.f / (1.f + log1pf(sE[tid*3 + j]));
            mx = fmaxf(mx, sc[j]);
        }
        float ss = 0.f;
        #pragma unroll
        for (int j = 0; j < 3; j++) { sc[j] = expf(sc[j] - mx); ss += sc[j]; }
        #pragma unroll
        for (int j = 0; j < 3; j++) sP[tid*3 + j] = sc[j] / ss;
    }
    __syncthreads();
    for (int t = tid; t < 3*324; t += 288) {
        int j = t / 324, e = t % 324;
        sMix[t] = sP[j*3+0]*sLV[e] + sP[j*3+1]*sLV[324+e] + sP[j*3+2]*sLV[648+e];
    }
    __syncthreads();
    if (warp < 3) {
        float* A  = &eigsm[warp*EW];
        float* Vv = A + 342;
        float* ev = Vv + 342;
        float* cs = ev + 18;
        float* sn = cs + 9;
        int*   pr = (int*)(sn + 9);
        int*   qr = pr + 9;
        for (int e = lane; e < 324; e += 32) A[(e/18)*19 + (e%18)] = sMix[warp*324 + e];
        __syncwarp();
        warp_jacobi18(A, Vv, cs, sn, pr, qr, lane, 8);
        for (int k = lane; k < 18; k += 32) ev[k] = fmaxf(A[k*19 + k], LN_RECT);
        __syncwarp();
        // pre-scale A[i][k] = Vv[i][k]*ev[k]  (reuses dead A buffer)
        for (int e = lane; e < 324; e += 32) {
            int i = e / 18, k = e % 18;
            A[i*19 + k] = Vv[i*19 + k] * ev[k];
        }
        __syncwarp();
        for (int t = lane; t < 171; t += 32) {
            int i = 0, rem = t;
            while (rem >= 18 - i) { rem -= 18 - i; i++; }
            int j = i + rem;
            float s = 0.f;
            #pragma unroll
            for (int k = 0; k < 18; k++) s += A[i*19 + k] * Vv[j*19 + k];
            g_vec[(size_t)b*VECLEN + warp*171 + t] = s;
        }
    }
}

// ------------------------------------------------------------- output head
__global__ void k_out(const float* __restrict__ Wl, const float* __restrict__ bl,
                      float* __restrict__ out) {
    int g = blockIdx.x * blockDim.x + threadIdx.x;
    if (g >= BS*4) return;
    int b = g >> 2, j = g & 3;
    float s = bl[j];
    const float* v = &g_vec[(size_t)b*VECLEN];
    for (int t = 0; t < VECLEN; t++) s += v[t] * Wl[t*4 + j];
    out[g] = s;
}

// ---------------------------------------------------------------------------
extern "C" void kernel_launch(void* const* d_in, const int* in_sizes, int n_in,
                              void* d_out, int out_size) {
    const float* x   = (const float*)d_in[0];
    const float* W1  = (const float*)d_in[1];
    const float* b1  = (const float*)d_in[2];
    const float* g1  = (const float*)d_in[3];
    const float* be1 = (const float*)d_in[4];
    const float* W2  = (const float*)d_in[5];
    const float* b2  = (const float*)d_in[6];
    const float* g2  = (const float*)d_in[7];
    const float* be2 = (const float*)d_in[8];
    const float* Wq  = (const float*)d_in[9];
    const float* Wk  = (const float*)d_in[10];
    const float* Wv  = (const float*)d_in[11];
    const float* Wl  = (const float*)d_in[12];
    const float* bl  = (const float*)d_in[13];
    float* out = (float*)d_out;

    k_zero<<<1, 128>>>();
    k_conv1<<<(BS*WIN + 255)/256, 256>>>(x, W1, b1);
    k_fin1<<<1, 32>>>(g1, be1);
    k_conv2<<<dim3((W2L + CTILE - 1)/CTILE, BS), 256>>>(W2, b2);
    k_fin2<<<1, 32>>>(g2, be2);
    k_cov<<<dim3(NEP, BS), 192>>>(Wq, Wk, Wv);
    k_eighlog<<<NMATQKV/8, 256>>>();
    k_attn<<<BS, 288>>>();
    k_out<<<(BS*4 + 255)/256, 256>>>(Wl, bl, out);
}

// round 8
// speedup vs baseline: 2.1874x; 2.1874x over previous
#include <cuda_runtime.h>
#include <math.h>

#define BS    2048
#define C1    22
#define WIN   438
#define C2    20
#define W2L   439
#define NIN   20
#define NOUT  18
#define NEP   3
#define KW    12
#define NMATQKV (BS*NEP*3)      // 18432 matrices (Q,K,V per (b,m))
#define VECLEN  513             // 3 * 171
#define LN_RECT (-9.2103403719761836f)  // log(1e-4)
#define NSWEEP  6

// ---------------- scratch (static device globals; no cudaMalloc allowed) ----
__device__ float g_h1[BS*C1*WIN];          // conv1 raw output
__device__ float g_h2[BS*C2*W2L];          // conv2 raw output
__device__ float g_spd[(size_t)NMATQKV*NOUT*NOUT];  // Q/K/V -> logm; Q slot reused for mixed
__device__ float g_vec[(size_t)BS*VECLEN];
__device__ float g_red[2*C1 + 2*C2];       // s1[22] q1[22] s2[20] q2[20]
__device__ float g_aff[2*C1 + 2*C2];       // a1[22] c1[22] a2[20] c2[20]

// ---------------------------------------------------------------- zero stats
__global__ void k_zero() {
    int t = threadIdx.x;
    if (t < 2*C1 + 2*C2) g_red[t] = 0.f;
}

// ------------------------------------------------------- conv1 + bn1 stats
__global__ void k_conv1(const float* __restrict__ x,
                        const float* __restrict__ W1,
                        const float* __restrict__ b1) {
    __shared__ float w1s[C1*C1];
    __shared__ float sS[C1], sQ[C1];
    int tid = threadIdx.x;
    for (int t = tid; t < C1*C1; t += blockDim.x) w1s[t] = W1[t];  // W1[o,0,h,0]
    if (tid < C1) { sS[tid] = 0.f; sQ[tid] = 0.f; }
    __syncthreads();

    int g = blockIdx.x * blockDim.x + tid;
    bool valid = (g < BS*WIN);
    int b = g / WIN, w = g % WIN;
    float xv[C1];
    if (valid) {
        #pragma unroll
        for (int h = 0; h < C1; h++) xv[h] = x[((size_t)b*C1 + h)*WIN + w];
    }
    for (int o = 0; o < C1; o++) {
        float acc = 0.f;
        if (valid) {
            acc = b1[o];
            #pragma unroll
            for (int h = 0; h < C1; h++) acc += xv[h] * w1s[o*C1 + h];
            g_h1[((size_t)b*C1 + o)*WIN + w] = acc;
        }
        float s = acc, q = acc*acc;
        #pragma unroll
        for (int d = 16; d; d >>= 1) {
            s += __shfl_xor_sync(0xffffffffu, s, d);
            q += __shfl_xor_sync(0xffffffffu, q, d);
        }
        if ((tid & 31) == 0) { atomicAdd(&sS[o], s); atomicAdd(&sQ[o], q); }
    }
    __syncthreads();
    if (tid < C1) {
        atomicAdd(&g_red[tid], sS[tid]);
        atomicAdd(&g_red[C1 + tid], sQ[tid]);
    }
}

__global__ void k_fin1(const float* __restrict__ g1, const float* __restrict__ be1) {
    int c = threadIdx.x;
    if (c >= C1) return;
    float cnt  = (float)((size_t)BS*WIN);
    float mean = g_red[c] / cnt;
    float var  = g_red[C1 + c] / cnt - mean*mean;
    float a = g1[c] * rsqrtf(var + 1e-5f);
    g_aff[c]      = a;
    g_aff[C1 + c] = be1[c] - mean*a;
}

// ------------------------------------------------------- conv2 + bn2 stats
#define CTILE 256
#define TPAD  267   // 256 + 11, odd stride (conflict-free)
__global__ __launch_bounds__(256) void k_conv2(const float* __restrict__ W2,
                                               const float* __restrict__ b2) {
    __shared__ float tile[C1*TPAD];     // 5874 floats
    __shared__ float w2s[C2*C1*KW];     // 5280 floats
    __shared__ float sS[C2], sQ[C2];
    int tid = threadIdx.x;
    int b  = blockIdx.y;
    int w0 = blockIdx.x * CTILE;

    for (int t = tid; t < C2*C1*KW; t += 256) w2s[t] = W2[t];
    if (tid < C2) { sS[tid] = 0.f; sQ[tid] = 0.f; }
    for (int t = tid; t < C1*TPAD; t += 256) {
        int i = t / TPAD, dw = t % TPAD;
        int gw = w0 - 6 + dw;
        float v = 0.f;
        if (gw >= 0 && gw < WIN)
            v = g_aff[i] * g_h1[((size_t)b*C1 + i)*WIN + gw] + g_aff[C1 + i];
        tile[t] = v;
    }
    __syncthreads();

    int o_grp = tid >> 6;        // 0..3 (warp-uniform)
    int widx  = tid & 63;
    int wl0   = widx * 4;

    float acc[20];
    #pragma unroll
    for (int oi = 0; oi < 5; oi++) {
        float bb = b2[o_grp*5 + oi];
        #pragma unroll
        for (int wj = 0; wj < 4; wj++) acc[oi*4 + wj] = bb;
    }
    for (int i = 0; i < C1; i++) {
        float tv[15];
        #pragma unroll
        for (int u = 0; u < 15; u++) tv[u] = tile[i*TPAD + wl0 + u];
        #pragma unroll
        for (int oi = 0; oi < 5; oi++) {
            int o = o_grp*5 + oi;
            #pragma unroll
            for (int k = 0; k < KW; k++) {
                float wv = w2s[(o*C1 + i)*KW + k];
                #pragma unroll
                for (int wj = 0; wj < 4; wj++) acc[oi*4 + wj] += tv[wj + k] * wv;
            }
        }
    }
    for (int oi = 0; oi < 5; oi++) {
        int o = o_grp*5 + oi;
        float s = 0.f, q = 0.f;
        #pragma unroll
        for (int wj = 0; wj < 4; wj++) {
            int w = w0 + wl0 + wj;
            if (w < W2L) {
                float v = acc[oi*4 + wj];
                g_h2[((size_t)b*C2 + o)*W2L + w] = v;
                s += v; q += v*v;
            }
        }
        #pragma unroll
        for (int d = 16; d; d >>= 1) {
            s += __shfl_xor_sync(0xffffffffu, s, d);
            q += __shfl_xor_sync(0xffffffffu, q, d);
        }
        if ((tid & 31) == 0) { atomicAdd(&sS[o], s); atomicAdd(&sQ[o], q); }
    }
    __syncthreads();
    if (tid < C2) {
        atomicAdd(&g_red[2*C1 + tid], sS[tid]);
        atomicAdd(&g_red[2*C1 + C2 + tid], sQ[tid]);
    }
}

__global__ void k_fin2(const float* __restrict__ g2, const float* __restrict__ be2) {
    int c = threadIdx.x;
    if (c >= C2) return;
    float cnt  = (float)((size_t)BS*W2L);
    float mean = g_red[2*C1 + c] / cnt;
    float var  = g_red[2*C1 + C2 + c] / cnt - mean*mean;
    float a = g2[c] * rsqrtf(var + 1e-5f);
    g_aff[2*C1 + c]      = a;
    g_aff[2*C1 + C2 + c] = be2[c] - mean*a;
}

// ----------------------------------------- covariance + Q/K/V congruence
#define SP 149   // row stride for sig (gcd(149,32)=1)
__global__ __launch_bounds__(192) void k_cov(const float* __restrict__ Wq,
                                             const float* __restrict__ Wk,
                                             const float* __restrict__ Wv) {
    __shared__ float sig[C2*SP];
    __shared__ float Cm[C2*C2];
    __shared__ float T[C2*NOUT];
    __shared__ float Ws[C2*NOUT];
    __shared__ float mean_s[C2];
    __shared__ float trs;
    const int offs[NEP] = {0, 147, 293};
    const int Ls[NEP]   = {147, 146, 146};
    int m = blockIdx.x, b = blockIdx.y;
    int off = offs[m], L = Ls[m];
    int tid = threadIdx.x;
    int warp = tid >> 5, lane = tid & 31;

    for (int t = tid; t < C2*L; t += 192) {
        int c = t / L, l = t % L;
        sig[c*SP + l] = g_aff[2*C1 + c] * g_h2[((size_t)b*C2 + c)*W2L + off + l]
                      + g_aff[2*C1 + C2 + c];
    }
    __syncthreads();
    for (int r = warp; r < C2; r += 6) {
        float s = 0.f;
        for (int l = lane; l < L; l += 32) s += sig[r*SP + l];
        #pragma unroll
        for (int d = 16; d; d >>= 1) s += __shfl_xor_sync(0xffffffffu, s, d);
        if (!lane) mean_s[r] = s / (float)L;
    }
    __syncthreads();
    for (int t = tid; t < C2*L; t += 192) sig[(t/L)*SP + (t%L)] -= mean_s[t/L];
    __syncthreads();
    for (int t = tid; t < 210; t += 192) {
        int p = 0, rem = t;
        while (rem >= C2 - p) { rem -= C2 - p; p++; }
        int q = p + rem;
        float s = 0.f;
        for (int l = 0; l < L; l++) s += sig[p*SP + l] * sig[q*SP + l];
        Cm[p*C2 + q] = s;
        Cm[q*C2 + p] = s;
    }
    __syncthreads();
    if (tid == 0) {
        float tr = 0.f;
        for (int i = 0; i < C2; i++) tr += Cm[i*C2 + i];
        trs = 1.f / tr;                    // (L-1) cancels in trace-normalization
    }
    __syncthreads();
    for (int t = tid; t < C2*C2; t += 192) {
        float v = Cm[t] * trs;
        if (t / C2 == t % C2) v += 1e-5f;
        Cm[t] = v;
    }
    __syncthreads();
    const float* Wp[3] = {Wq, Wk, Wv};
    for (int which = 0; which < 3; which++) {
        for (int t = tid; t < C2*NOUT; t += 192) Ws[t] = Wp[which][t];
        __syncthreads();
        for (int t = tid; t < C2*NOUT; t += 192) {
            int p = t / NOUT, j = t % NOUT;
            float s = 0.f;
            #pragma unroll
            for (int q = 0; q < C2; q++) s += Cm[p*C2 + q] * Ws[q*NOUT + j];
            T[t] = s;
        }
        __syncthreads();
        float* dst = &g_spd[((size_t)(b*NEP + m)*3 + which)*NOUT*NOUT];
        for (int t = tid; t < NOUT*NOUT; t += 192) {
            int i = t / NOUT, j = t % NOUT;
            float s = 0.f;
            #pragma unroll
            for (int p = 0; p < C2; p++) s += Ws[p*NOUT + i] * T[p*NOUT + j];
            dst[t] = s;
        }
        __syncthreads();
    }
}

// ------------------------------ warp-level parallel-round Jacobi (18x18)
// A, Vv: 18x18 in smem with row stride 19. cs/sn: 9 floats, pr/qr: 9 ints.
// Lane->item mapping (pair index pi, element k) is round-invariant:
// precomputed once; rotation params loaded once per round, reused in both phases.
__device__ __forceinline__ void warp_jacobi18(float* A, float* Vv,
                                              float* cs, float* sn,
                                              int* pr, int* qr,
                                              int lane, int nsweep) {
    #pragma unroll
    for (int it = 0; it < 11; it++) {
        int e = lane + 32*it;
        if (it < 10 || e < 324)
            Vv[(e/18)*19 + (e%18)] = (e/18 == e%18) ? 1.f : 0.f;
    }
    __syncwarp();

    // per-lane round-invariant item indices (162 items over 6 iterations)
    int piv[6], kkA[6], kkV[6];
    #pragma unroll
    for (int it = 0; it < 6; it++) {
        int t = lane + 32*it;
        if (t > 161) t = 161;                 // clamped lanes never store (va5 guard)
        piv[it] = t / 18;
        kkA[it] = t % 18;
        kkV[it] = (t % 18) * 19;
    }
    const bool va5 = (lane + 160) < 162;

    for (int sw = 0; sw < nsweep; sw++) {
        for (int r = 0; r < 17; r++) {
            if (lane < 9) {
                int a  = (lane == 0) ? 0 : (1 + ((lane - 1 + r) % 17));
                int jj = 17 - lane;
                int bb = 1 + ((jj - 1 + r) % 17);
                int p = a < bb ? a : bb;
                int q = a < bb ? bb : a;
                float app = A[p*19 + p], aqq = A[q*19 + q], apq = A[p*19 + q];
                float c = 1.f, s = 0.f;
                if (fabsf(apq) > 1e-36f) {
                    float tau = (aqq - app) / (2.f * apq);
                    float tt  = 1.f / (fabsf(tau) + sqrtf(1.f + tau*tau));
                    if (tau < 0.f) tt = -tt;
                    c = rsqrtf(1.f + tt*tt);
                    s = tt * c;
                }
                pr[lane] = p; qr[lane] = q; cs[lane] = c; sn[lane] = s;
            }
            __syncwarp();
            // fetch params once per round, keep for both phases
            int pR[6], qR[6]; float cR[6], sR[6];
            #pragma unroll
            for (int it = 0; it < 6; it++) {
                int pi = piv[it];
                pR[it] = pr[pi]; qR[it] = qr[pi];
                cR[it] = cs[pi]; sR[it] = sn[pi];
            }
            // phase 1: row rotations on A (J^T A) + column rotations on V (V J)
            #pragma unroll
            for (int it = 0; it < 6; it++) {
                if (it == 5 && !va5) break;
                int p = pR[it], q = qR[it];
                float c = cR[it], s = sR[it];
                float* Ap = &A[p*19]; float* Aq = &A[q*19];
                int k = kkA[it];
                float apk = Ap[k], aqk = Aq[k];
                Ap[k] = c*apk - s*aqk;
                Aq[k] = s*apk + c*aqk;
                float* Vk = &Vv[kkV[it]];
                float vkp = Vk[p], vkq = Vk[q];
                Vk[p] = c*vkp - s*vkq;
                Vk[q] = s*vkp + c*vkq;
            }
            __syncwarp();
            // phase 2: column rotations on A  ((J^T A) J)
            #pragma unroll
            for (int it = 0; it < 6; it++) {
                if (it == 5 && !va5) break;
                int p = pR[it], q = qR[it];
                float c = cR[it], s = sR[it];
                float* Ak = &A[kkV[it]];
                float akp = Ak[p], akq = Ak[q];
                Ak[p] = c*akp - s*akq;
                Ak[q] = s*akp + c*akq;
            }
            __syncwarp();
        }
    }
}

// --------------------------------------- eigh + log for all Q/K/V matrices
#define EW 768
__global__ __launch_bounds__(256) void k_eighlog() {
    __shared__ float sm[8*EW];
    int wid = threadIdx.x >> 5, lane = threadIdx.x & 31;
    size_t mat = (size_t)blockIdx.x * 8 + wid;
    float* A  = &sm[wid*EW];
    float* Vv = A + 342;
    float* ev = Vv + 342;
    float* cs = ev + 18;
    float* sn = cs + 9;
    int*   pr = (int*)(sn + 9);
    int*   qr = pr + 9;
    float* src = &g_spd[mat * 324];
    for (int e = lane; e < 324; e += 32) A[(e/18)*19 + (e%18)] = src[e];
    __syncwarp();
    warp_jacobi18(A, Vv, cs, sn, pr, qr, lane, NSWEEP);
    for (int k = lane; k < 18; k += 32) ev[k] = logf(fmaxf(A[k*19 + k], 1e-38f));
    __syncwarp();
    // pre-scale: A[i][k] = Vv[i][k] * ev[k]  (A dead; single FFMA per k below)
    for (int e = lane; e < 324; e += 32) {
        int i = e / 18, k = e % 18;
        A[i*19 + k] = Vv[i*19 + k] * ev[k];
    }
    __syncwarp();
    for (int e = lane; e < 324; e += 32) {
        int i = e / 18, j = e % 18;
        float s = 0.f;
        #pragma unroll
        for (int k = 0; k < 18; k++) s += A[i*19 + k] * Vv[j*19 + k];
        src[e] = s;  // overwrite with log-matrix
    }
}

// ------------- attention mix: energies, softmax, mix -> write into Q slots
__global__ __launch_bounds__(288) void k_attn_mix() {
    __shared__ float sLQ[3*324], sLK[3*324], sLV[3*324];
    __shared__ float sE[9], sP[9];
    int b = blockIdx.x, tid = threadIdx.x;
    int warp = tid >> 5, lane = tid & 31;
    size_t base = (size_t)b * 9 * 324;
    for (int t = tid; t < 3*324; t += 288) {
        int mm = t / 324, e = t % 324;
        sLQ[t] = g_spd[base + (mm*3 + 0)*324 + e];
        sLK[t] = g_spd[base + (mm*3 + 1)*324 + e];
        sLV[t] = g_spd[base + (mm*3 + 2)*324 + e];
    }
    __syncthreads();
    {   // 9 warps -> 9 (i,j) energy pairs
        int i = warp / 3, j = warp % 3;
        float s = 0.f;
        for (int e = lane; e < 324; e += 32) {
            float d = sLQ[i*324 + e] - sLK[j*324 + e];
            s += d*d;
        }
        #pragma unroll
        for (int d = 16; d; d >>= 1) s += __shfl_xor_sync(0xffffffffu, s, d);
        if (!lane) sE[i*3 + j] = s;
    }
    __syncthreads();
    if (tid < 3) {
        float sc[3]; float mx = -1e30f;
        #pragma unroll
        for (int j = 0; j < 3; j++) {
            sc[j] = 1.f / (1.f + log1pf(sE[tid*3 + j]));
            mx = fmaxf(mx, sc[j]);
        }
        float ss = 0.f;
        #pragma unroll
        for (int j = 0; j < 3; j++) { sc[j] = expf(sc[j] - mx); ss += sc[j]; }
        #pragma unroll
        for (int j = 0; j < 3; j++) sP[tid*3 + j] = sc[j] / ss;
    }
    __syncthreads();
    // mixed[j] = sum_i P[j,i] logV[i]  -> overwrite the (dead) logQ slot (j*3+0)
    for (int t = tid; t < 3*324; t += 288) {
        int j = t / 324, e = t % 324;
        float v = sP[j*3+0]*sLV[e] + sP[j*3+1]*sLV[324+e] + sP[j*3+2]*sLV[648+e];
        g_spd[base + (j*3 + 0)*324 + e] = v;
    }
}

// ------------- eigh(mixed) + rect-log + triu-vec (full 8-warp occupancy)
// identity: log(spd_rect(spd_exp(M), eps)) = U diag(max(s, log(eps))) U^T
__global__ __launch_bounds__(256) void k_eighfin() {
    __shared__ float sm[8*EW];
    int wid = threadIdx.x >> 5, lane = threadIdx.x & 31;
    int mat = blockIdx.x * 8 + wid;       // 0..6143: (b,m)
    int b = mat / 3, m = mat % 3;
    float* A  = &sm[wid*EW];
    float* Vv = A + 342;
    float* ev = Vv + 342;
    float* cs = ev + 18;
    float* sn = cs + 9;
    int*   pr = (int*)(sn + 9);
    int*   qr = pr + 9;
    const float* src = &g_spd[((size_t)b*9 + m*3 + 0)*324];
    for (int e = lane; e < 324; e += 32) A[(e/18)*19 + (e%18)] = src[e];
    __syncwarp();
    warp_jacobi18(A, Vv, cs, sn, pr, qr, lane, NSWEEP);
    for (int k = lane; k < 18; k += 32) ev[k] = fmaxf(A[k*19 + k], LN_RECT);
    __syncwarp();
    for (int e = lane; e < 324; e += 32) {
        int i = e / 18, k = e % 18;
        A[i*19 + k] = Vv[i*19 + k] * ev[k];
    }
    __syncwarp();
    for (int t = lane; t < 171; t += 32) {
        int i = 0, rem = t;
        while (rem >= 18 - i) { rem -= 18 - i; i++; }
        int j = i + rem;
        float s = 0.f;
        #pragma unroll
        for (int k = 0; k < 18; k++) s += A[i*19 + k] * Vv[j*19 + k];
        g_vec[(size_t)b*VECLEN + m*171 + t] = s;
    }
}

// ------------------------------------------------------------- output head
__global__ void k_out(const float* __restrict__ Wl, const float* __restrict__ bl,
                      float* __restrict__ out) {
    int g = blockIdx.x * blockDim.x + threadIdx.x;
    if (g >= BS*4) return;
    int b = g >> 2, j = g & 3;
    float s = bl[j];
    const float* v = &g_vec[(size_t)b*VECLEN];
    for (int t = 0; t < VECLEN; t++) s += v[t] * Wl[t*4 + j];
    out[g] = s;
}

// ---------------------------------------------------------------------------
extern "C" void kernel_launch(void* const* d_in, const int* in_sizes, int n_in,
                              void* d_out, int out_size) {
    const float* x   = (const float*)d_in[0];
    const float* W1  = (const float*)d_in[1];
    const float* b1  = (const float*)d_in[2];
    const float* g1  = (const float*)d_in[3];
    const float* be1 = (const float*)d_in[4];
    const float* W2  = (const float*)d_in[5];
    const float* b2  = (const float*)d_in[6];
    const float* g2  = (const float*)d_in[7];
    const float* be2 = (const float*)d_in[8];
    const float* Wq  = (const float*)d_in[9];
    const float* Wk  = (const float*)d_in[10];
    const float* Wv  = (const float*)d_in[11];
    const float* Wl  = (const float*)d_in[12];
    const float* bl  = (const float*)d_in[13];
    float* out = (float*)d_out;

    k_zero<<<1, 128>>>();
    k_conv1<<<(BS*WIN + 255)/256, 256>>>(x, W1, b1);
    k_fin1<<<1, 32>>>(g1, be1);
    k_conv2<<<dim3((W2L + CTILE - 1)/CTILE, BS), 256>>>(W2, b2);
    k_fin2<<<1, 32>>>(g2, be2);
    k_cov<<<dim3(NEP, BS), 192>>>(Wq, Wk, Wv);
    k_eighlog<<<NMATQKV/8, 256>>>();
    k_attn_mix<<<BS, 288>>>();
    k_eighfin<<<(BS*NEP)/8, 256>>>();
    k_out<<<(BS*4 + 255)/256, 256>>>(Wl, bl, out);
}

// round 12
// speedup vs baseline: 2.4853x; 1.1362x over previous
#include <cuda_runtime.h>
#include <math.h>

#define BS    2048
#define C1    22
#define WIN   438
#define C2    20
#define W2L   439
#define NIN   20
#define NOUT  18
#define NEP   3
#define KW    12
#define NMATQKV (BS*NEP*3)      // 18432 matrices (Q,K,V per (b,m))
#define VECLEN  513             // 3 * 171
#define LN_RECT (-9.2103403719761836f)  // log(1e-4)
#define NSWEEP  5

// ---------------- scratch (static device globals; no cudaMalloc allowed) ----
__device__ float g_h1[BS*C1*WIN];          // conv1 raw output
__device__ float g_h2[BS*C2*W2L];          // conv2 raw output
__device__ float g_spd[(size_t)NMATQKV*NOUT*NOUT];  // Q/K/V -> logm; Q slot reused for mixed
__device__ float g_vec[(size_t)BS*VECLEN];
__device__ float g_red[2*C1 + 2*C2];       // s1[22] q1[22] s2[20] q2[20]
__device__ float g_aff[2*C1 + 2*C2];       // a1[22] c1[22] a2[20] c2[20]

// ---------------------------------------------------------------- zero stats
__global__ void k_zero() {
    int t = threadIdx.x;
    if (t < 2*C1 + 2*C2) g_red[t] = 0.f;
}

// ------------------------------------------------------- conv1 + bn1 stats
__global__ void k_conv1(const float* __restrict__ x,
                        const float* __restrict__ W1,
                        const float* __restrict__ b1) {
    __shared__ float w1s[C1*C1];
    __shared__ float sS[C1], sQ[C1];
    int tid = threadIdx.x;
    for (int t = tid; t < C1*C1; t += blockDim.x) w1s[t] = W1[t];  // W1[o,0,h,0]
    if (tid < C1) { sS[tid] = 0.f; sQ[tid] = 0.f; }
    __syncthreads();

    int g = blockIdx.x * blockDim.x + tid;
    bool valid = (g < BS*WIN);
    int b = g / WIN, w = g % WIN;
    float xv[C1];
    if (valid) {
        #pragma unroll
        for (int h = 0; h < C1; h++) xv[h] = x[((size_t)b*C1 + h)*WIN + w];
    }
    for (int o = 0; o < C1; o++) {
        float acc = 0.f;
        if (valid) {
            acc = b1[o];
            #pragma unroll
            for (int h = 0; h < C1; h++) acc += xv[h] * w1s[o*C1 + h];
            g_h1[((size_t)b*C1 + o)*WIN + w] = acc;
        }
        float s = acc, q = acc*acc;
        #pragma unroll
        for (int d = 16; d; d >>= 1) {
            s += __shfl_xor_sync(0xffffffffu, s, d);
            q += __shfl_xor_sync(0xffffffffu, q, d);
        }
        if ((tid & 31) == 0) { atomicAdd(&sS[o], s); atomicAdd(&sQ[o], q); }
    }
    __syncthreads();
    if (tid < C1) {
        atomicAdd(&g_red[tid], sS[tid]);
        atomicAdd(&g_red[C1 + tid], sQ[tid]);
    }
}

__global__ void k_fin1(const float* __restrict__ g1, const float* __restrict__ be1) {
    int c = threadIdx.x;
    if (c >= C1) return;
    float cnt  = (float)((size_t)BS*WIN);
    float mean = g_red[c] / cnt;
    float var  = g_red[C1 + c] / cnt - mean*mean;
    float a = g1[c] * rsqrtf(var + 1e-5f);
    g_aff[c]      = a;
    g_aff[C1 + c] = be1[c] - mean*a;
}

// ------------------------------------------------------- conv2 + bn2 stats
#define CTILE 256
#define TPAD  267   // 256 + 11, odd stride (conflict-free)
__global__ __launch_bounds__(256) void k_conv2(const float* __restrict__ W2,
                                               const float* __restrict__ b2) {
    __shared__ float tile[C1*TPAD];     // 5874 floats
    __shared__ float w2s[C2*C1*KW];     // 5280 floats
    __shared__ float sS[C2], sQ[C2];
    int tid = threadIdx.x;
    int b  = blockIdx.y;
    int w0 = blockIdx.x * CTILE;

    for (int t = tid; t < C2*C1*KW; t += 256) w2s[t] = W2[t];
    if (tid < C2) { sS[tid] = 0.f; sQ[tid] = 0.f; }
    for (int t = tid; t < C1*TPAD; t += 256) {
        int i = t / TPAD, dw = t % TPAD;
        int gw = w0 - 6 + dw;
        float v = 0.f;
        if (gw >= 0 && gw < WIN)
            v = g_aff[i] * g_h1[((size_t)b*C1 + i)*WIN + gw] + g_aff[C1 + i];
        tile[t] = v;
    }
    __syncthreads();

    int o_grp = tid >> 6;        // 0..3 (warp-uniform)
    int widx  = tid & 63;
    int wl0   = widx * 4;

    float acc[20];
    #pragma unroll
    for (int oi = 0; oi < 5; oi++) {
        float bb = b2[o_grp*5 + oi];
        #pragma unroll
        for (int wj = 0; wj < 4; wj++) acc[oi*4 + wj] = bb;
    }
    for (int i = 0; i < C1; i++) {
        float tv[15];
        #pragma unroll
        for (int u = 0; u < 15; u++) tv[u] = tile[i*TPAD + wl0 + u];
        #pragma unroll
        for (int oi = 0; oi < 5; oi++) {
            int o = o_grp*5 + oi;
            #pragma unroll
            for (int k = 0; k < KW; k++) {
                float wv = w2s[(o*C1 + i)*KW + k];
                #pragma unroll
                for (int wj = 0; wj < 4; wj++) acc[oi*4 + wj] += tv[wj + k] * wv;
            }
        }
    }
    for (int oi = 0; oi < 5; oi++) {
        int o = o_grp*5 + oi;
        float s = 0.f, q = 0.f;
        #pragma unroll
        for (int wj = 0; wj < 4; wj++) {
            int w = w0 + wl0 + wj;
            if (w < W2L) {
                float v = acc[oi*4 + wj];
                g_h2[((size_t)b*C2 + o)*W2L + w] = v;
                s += v; q += v*v;
            }
        }
        #pragma unroll
        for (int d = 16; d; d >>= 1) {
            s += __shfl_xor_sync(0xffffffffu, s, d);
            q += __shfl_xor_sync(0xffffffffu, q, d);
        }
        if ((tid & 31) == 0) { atomicAdd(&sS[o], s); atomicAdd(&sQ[o], q); }
    }
    __syncthreads();
    if (tid < C2) {
        atomicAdd(&g_red[2*C1 + tid], sS[tid]);
        atomicAdd(&g_red[2*C1 + C2 + tid], sQ[tid]);
    }
}

__global__ void k_fin2(const float* __restrict__ g2, const float* __restrict__ be2) {
    int c = threadIdx.x;
    if (c >= C2) return;
    float cnt  = (float)((size_t)BS*W2L);
    float mean = g_red[2*C1 + c] / cnt;
    float var  = g_red[2*C1 + C2 + c] / cnt - mean*mean;
    float a = g2[c] * rsqrtf(var + 1e-5f);
    g_aff[2*C1 + c]      = a;
    g_aff[2*C1 + C2 + c] = be2[c] - mean*a;
}

// ----------------------------------------- covariance + Q/K/V congruence
#define SP 149   // row stride for sig (gcd(149,32)=1)
__global__ __launch_bounds__(192) void k_cov(const float* __restrict__ Wq,
                                             const float* __restrict__ Wk,
                                             const float* __restrict__ Wv) {
    __shared__ float sig[C2*SP];
    __shared__ float Cm[C2*C2];
    __shared__ float T[C2*NOUT];
    __shared__ float Ws[C2*NOUT];
    __shared__ float mean_s[C2];
    __shared__ float trs;
    const int offs[NEP] = {0, 147, 293};
    const int Ls[NEP]   = {147, 146, 146};
    int m = blockIdx.x, b = blockIdx.y;
    int off = offs[m], L = Ls[m];
    int tid = threadIdx.x;
    int warp = tid >> 5, lane = tid & 31;

    for (int t = tid; t < C2*L; t += 192) {
        int c = t / L, l = t % L;
        sig[c*SP + l] = g_aff[2*C1 + c] * g_h2[((size_t)b*C2 + c)*W2L + off + l]
                      + g_aff[2*C1 + C2 + c];
    }
    __syncthreads();
    for (int r = warp; r < C2; r += 6) {
        float s = 0.f;
        for (int l = lane; l < L; l += 32) s += sig[r*SP + l];
        #pragma unroll
        for (int d = 16; d; d >>= 1) s += __shfl_xor_sync(0xffffffffu, s, d);
        if (!lane) mean_s[r] = s / (float)L;
    }
    __syncthreads();
    for (int t = tid; t < C2*L; t += 192) sig[(t/L)*SP + (t%L)] -= mean_s[t/L];
    __syncthreads();
    for (int t = tid; t < 210; t += 192) {
        int p = 0, rem = t;
        while (rem >= C2 - p) { rem -= C2 - p; p++; }
        int q = p + rem;
        float s = 0.f;
        for (int l = 0; l < L; l++) s += sig[p*SP + l] * sig[q*SP + l];
        Cm[p*C2 + q] = s;
        Cm[q*C2 + p] = s;
    }
    __syncthreads();
    if (tid == 0) {
        float tr = 0.f;
        for (int i = 0; i < C2; i++) tr += Cm[i*C2 + i];
        trs = 1.f / tr;                    // (L-1) cancels in trace-normalization
    }
    __syncthreads();
    for (int t = tid; t < C2*C2; t += 192) {
        float v = Cm[t] * trs;
        if (t / C2 == t % C2) v += 1e-5f;
        Cm[t] = v;
    }
    __syncthreads();
    const float* Wp[3] = {Wq, Wk, Wv};
    for (int which = 0; which < 3; which++) {
        for (int t = tid; t < C2*NOUT; t += 192) Ws[t] = Wp[which][t];
        __syncthreads();
        for (int t = tid; t < C2*NOUT; t += 192) {
            int p = t / NOUT, j = t % NOUT;
            float s = 0.f;
            #pragma unroll
            for (int q = 0; q < C2; q++) s += Cm[p*C2 + q] * Ws[q*NOUT + j];
            T[t] = s;
        }
        __syncthreads();
        float* dst = &g_spd[((size_t)(b*NEP + m)*3 + which)*NOUT*NOUT];
        for (int t = tid; t < NOUT*NOUT; t += 192) {
            int i = t / NOUT, j = t % NOUT;
            float s = 0.f;
            #pragma unroll
            for (int p = 0; p < C2; p++) s += Ws[p*NOUT + i] * T[p*NOUT + j];
            dst[t] = s;
        }
        __syncthreads();
    }
}

// ------------------------------ warp-level parallel-round Jacobi (18x18)
// A, Vv: 18x18 in smem with row stride 19. cs/sn: 9 floats, pr/qr: 9 ints.
// PROVEN implementation (R8 pass @ rel_err 9.58e-6).
__device__ __forceinline__ void warp_jacobi18(float* A, float* Vv,
                                              float* cs, float* sn,
                                              int* pr, int* qr,
                                              int lane, int nsweep) {
    #pragma unroll
    for (int it = 0; it < 11; it++) {
        int e = lane + 32*it;
        if (it < 10 || e < 324)
            Vv[(e/18)*19 + (e%18)] = (e/18 == e%18) ? 1.f : 0.f;
    }
    __syncwarp();

    // per-lane round-invariant item indices (162 items over 6 iterations)
    int piv[6], kkA[6], kkV[6];
    #pragma unroll
    for (int it = 0; it < 6; it++) {
        int t = lane + 32*it;
        if (t > 161) t = 161;                 // clamped lanes never store (va5 guard)
        piv[it] = t / 18;
        kkA[it] = t % 18;
        kkV[it] = (t % 18) * 19;
    }
    const bool va5 = (lane + 160) < 162;

    for (int sw = 0; sw < nsweep; sw++) {
        for (int r = 0; r < 17; r++) {
            if (lane < 9) {
                int a  = (lane == 0) ? 0 : (1 + ((lane - 1 + r) % 17));
                int jj = 17 - lane;
                int bb = 1 + ((jj - 1 + r) % 17);
                int p = a < bb ? a : bb;
                int q = a < bb ? bb : a;
                float app = A[p*19 + p], aqq = A[q*19 + q], apq = A[p*19 + q];
                float c = 1.f, s = 0.f;
                if (fabsf(apq) > 1e-36f) {
                    float tau = (aqq - app) / (2.f * apq);
                    float tt  = 1.f / (fabsf(tau) + sqrtf(1.f + tau*tau));
                    if (tau < 0.f) tt = -tt;
                    c = rsqrtf(1.f + tt*tt);
                    s = tt * c;
                }
                pr[lane] = p; qr[lane] = q; cs[lane] = c; sn[lane] = s;
            }
            __syncwarp();
            // fetch params once per round, keep for both phases
            int pR[6], qR[6]; float cR[6], sR[6];
            #pragma unroll
            for (int it = 0; it < 6; it++) {
                int pi = piv[it];
                pR[it] = pr[pi]; qR[it] = qr[pi];
                cR[it] = cs[pi]; sR[it] = sn[pi];
            }
            // phase 1: row rotations on A (J^T A) + column rotations on V (V J)
            #pragma unroll
            for (int it = 0; it < 6; it++) {
                if (it == 5 && !va5) break;
                int p = pR[it], q = qR[it];
                float c = cR[it], s = sR[it];
                float* Ap = &A[p*19]; float* Aq = &A[q*19];
                int k = kkA[it];
                float apk = Ap[k], aqk = Aq[k];
                Ap[k] = c*apk - s*aqk;
                Aq[k] = s*apk + c*aqk;
                float* Vk = &Vv[kkV[it]];
                float vkp = Vk[p], vkq = Vk[q];
                Vk[p] = c*vkp - s*vkq;
                Vk[q] = s*vkp + c*vkq;
            }
            __syncwarp();
            // phase 2: column rotations on A  ((J^T A) J)
            #pragma unroll
            for (int it = 0; it < 6; it++) {
                if (it == 5 && !va5) break;
                int p = pR[it], q = qR[it];
                float c = cR[it], s = sR[it];
                float* Ak = &A[kkV[it]];
                float akp = Ak[p], akq = Ak[q];
                Ak[p] = c*akp - s*akq;
                Ak[q] = s*akp + c*akq;
            }
            __syncwarp();
        }
    }
}

// --------------------------------------- eigh + log for all Q/K/V matrices
#define EW 768
__global__ __launch_bounds__(256) void k_eighlog() {
    __shared__ float sm[8*EW];
    int wid = threadIdx.x >> 5, lane = threadIdx.x & 31;
    size_t mat = (size_t)blockIdx.x * 8 + wid;
    float* A  = &sm[wid*EW];
    float* Vv = A + 342;
    float* ev = Vv + 342;
    float* cs = ev + 18;
    float* sn = cs + 9;
    int*   pr = (int*)(sn + 9);
    int*   qr = pr + 9;
    float* src = &g_spd[mat * 324];
    for (int e = lane; e < 324; e += 32) A[(e/18)*19 + (e%18)] = src[e];
    __syncwarp();
    warp_jacobi18(A, Vv, cs, sn, pr, qr, lane, NSWEEP);
    for (int k = lane; k < 18; k += 32) ev[k] = logf(fmaxf(A[k*19 + k], 1e-38f));
    __syncwarp();
    // pre-scale: A[i][k] = Vv[i][k] * ev[k]  (A dead; single FFMA per k below)
    for (int e = lane; e < 324; e += 32) {
        int i = e / 18, k = e % 18;
        A[i*19 + k] = Vv[i*19 + k] * ev[k];
    }
    __syncwarp();
    for (int e = lane; e < 324; e += 32) {
        int i = e / 18, j = e % 18;
        float s = 0.f;
        #pragma unroll
        for (int k = 0; k < 18; k++) s += A[i*19 + k] * Vv[j*19 + k];
        src[e] = s;  // overwrite with log-matrix
    }
}

// ------------- attention mix: energies, softmax, mix -> write into Q slots
__global__ __launch_bounds__(288) void k_attn_mix() {
    __shared__ float sLQ[3*324], sLK[3*324], sLV[3*324];
    __shared__ float sE[9], sP[9];
    int b = blockIdx.x, tid = threadIdx.x;
    int warp = tid >> 5, lane = tid & 31;
    size_t base = (size_t)b * 9 * 324;
    for (int t = tid; t < 3*324; t += 288) {
        int mm = t / 324, e = t % 324;
        sLQ[t] = g_spd[base + (mm*3 + 0)*324 + e];
        sLK[t] = g_spd[base + (mm*3 + 1)*324 + e];
        sLV[t] = g_spd[base + (mm*3 + 2)*324 + e];
    }
    __syncthreads();
    {   // 9 warps -> 9 (i,j) energy pairs
        int i = warp / 3, j = warp % 3;
        float s = 0.f;
        for (int e = lane; e < 324; e += 32) {
            float d = sLQ[i*324 + e] - sLK[j*324 + e];
            s += d*d;
        }
        #pragma unroll
        for (int d = 16; d; d >>= 1) s += __shfl_xor_sync(0xffffffffu, s, d);
        if (!lane) sE[i*3 + j] = s;
    }
    __syncthreads();
    if (tid < 3) {
        float sc[3]; float mx = -1e30f;
        #pragma unroll
        for (int j = 0; j < 3; j++) {
            sc[j] = 1.f / (1.f + log1pf(sE[tid*3 + j]));
            mx = fmaxf(mx, sc[j]);
        }
        float ss = 0.f;
        #pragma unroll
        for (int j = 0; j < 3; j++) { sc[j] = expf(sc[j] - mx); ss += sc[j]; }
        #pragma unroll
        for (int j = 0; j < 3; j++) sP[tid*3 + j] = sc[j] / ss;
    }
    __syncthreads();
    // mixed[j] = sum_i P[j,i] logV[i]  -> overwrite the (dead) logQ slot (j*3+0)
    for (int t = tid; t < 3*324; t += 288) {
        int j = t / 324, e = t % 324;
        float v = sP[j*3+0]*sLV[e] + sP[j*3+1]*sLV[324+e] + sP[j*3+2]*sLV[648+e];
        g_spd[base + (j*3 + 0)*324 + e] = v;
    }
}

// ------------- eigh(mixed) + rect-log + triu-vec (full 8-warp occupancy)
// identity: log(spd_rect(spd_exp(M), eps)) = U diag(max(s, log(eps))) U^T
__global__ __launch_bounds__(256) void k_eighfin() {
    __shared__ float sm[8*EW];
    int wid = threadIdx.x >> 5, lane = threadIdx.x & 31;
    int mat = blockIdx.x * 8 + wid;       // 0..6143: (b,m)
    int b = mat / 3, m = mat % 3;
    float* A  = &sm[wid*EW];
    float* Vv = A + 342;
    float* ev = Vv + 342;
    float* cs = ev + 18;
    float* sn = cs + 9;
    int*   pr = (int*)(sn + 9);
    int*   qr = pr + 9;
    const float* src = &g_spd[((size_t)b*9 + m*3 + 0)*324];
    for (int e = lane; e < 324; e += 32) A[(e/18)*19 + (e%18)] = src[e];
    __syncwarp();
    warp_jacobi18(A, Vv, cs, sn, pr, qr, lane, NSWEEP);
    for (int k = lane; k < 18; k += 32) ev[k] = fmaxf(A[k*19 + k], LN_RECT);
    __syncwarp();
    for (int e = lane; e < 324; e += 32) {
        int i = e / 18, k = e % 18;
        A[i*19 + k] = Vv[i*19 + k] * ev[k];
    }
    __syncwarp();
    for (int t = lane; t < 171; t += 32) {
        int i = 0, rem = t;
        while (rem >= 18 - i) { rem -= 18 - i; i++; }
        int j = i + rem;
        float s = 0.f;
        #pragma unroll
        for (int k = 0; k < 18; k++) s += A[i*19 + k] * Vv[j*19 + k];
        g_vec[(size_t)b*VECLEN + m*171 + t] = s;
    }
}

// ------------------------------------------------------------- output head
__global__ void k_out(const float* __restrict__ Wl, const float* __restrict__ bl,
                      float* __restrict__ out) {
    int g = blockIdx.x * blockDim.x + threadIdx.x;
    if (g >= BS*4) return;
    int b = g >> 2, j = g & 3;
    float s = bl[j];
    const float* v = &g_vec[(size_t)b*VECLEN];
    for (int t = 0; t < VECLEN; t++) s += v[t] * Wl[t*4 + j];
    out[g] = s;
}

// ---------------------------------------------------------------------------
extern "C" void kernel_launch(void* const* d_in, const int* in_sizes, int n_in,
                              void* d_out, int out_size) {
    const float* x   = (const float*)d_in[0];
    const float* W1  = (const float*)d_in[1];
    const float* b1  = (const float*)d_in[2];
    const float* g1  = (const float*)d_in[3];
    const float* be1 = (const float*)d_in[4];
    const float* W2  = (const float*)d_in[5];
    const float* b2  = (const float*)d_in[6];
    const float* g2  = (const float*)d_in[7];
    const float* be2 = (const float*)d_in[8];
    const float* Wq  = (const float*)d_in[9];
    const float* Wk  = (const float*)d_in[10];
    const float* Wv  = (const float*)d_in[11];
    const float* Wl  = (const float*)d_in[12];
    const float* bl  = (const float*)d_in[13];
    float* out = (float*)d_out;

    k_zero<<<1, 128>>>();
    k_conv1<<<(BS*WIN + 255)/256, 256>>>(x, W1, b1);
    k_fin1<<<1, 32>>>(g1, be1);
    k_conv2<<<dim3((W2L + CTILE - 1)/CTILE, BS), 256>>>(W2, b2);
    k_fin2<<<1, 32>>>(g2, be2);
    k_cov<<<dim3(NEP, BS), 192>>>(Wq, Wk, Wv);
    k_eighlog<<<NMATQKV/8, 256>>>();
    k_attn_mix<<<BS, 288>>>();
    k_eighfin<<<(BS*NEP)/8, 256>>>();
    k_out<<<(BS*4 + 255)/256, 256>>>(Wl, bl, out);
}

// round 14
// speedup vs baseline: 2.8785x; 1.1582x over previous
#include <cuda_runtime.h>
#include <math.h>

#define BS    2048
#define C1    22
#define WIN   438
#define C2    20
#define W2L   439
#define NIN   20
#define NOUT  18
#define NEP   3
#define KW    12
#define NMATQKV (BS*NEP*3)      // 18432 matrices (Q,K,V per (b,m))
#define VECLEN  513             // 3 * 171
#define LN_RECT (-9.2103403719761836f)  // log(1e-4)
#define NSWEEP  4

// ---------------- scratch (static device globals; no cudaMalloc allowed) ----
__device__ float g_h1[BS*C1*WIN];          // conv1 raw output
__device__ float g_h2[BS*C2*W2L];          // conv2 raw output
__device__ float g_spd[(size_t)NMATQKV*NOUT*NOUT];  // Q/K/V -> logm; Q slot reused for mixed
__device__ float g_vec[(size_t)BS*VECLEN];
__device__ float g_red[2*C1 + 2*C2];       // s1[22] q1[22] s2[20] q2[20]
__device__ float g_aff[2*C1 + 2*C2];       // a1[22] c1[22] a2[20] c2[20]

// ---------------------------------------------------------------- zero stats
__global__ void k_zero() {
    int t = threadIdx.x;
    if (t < 2*C1 + 2*C2) g_red[t] = 0.f;
}

// ------------------------------------------------------- conv1 + bn1 stats
__global__ void k_conv1(const float* __restrict__ x,
                        const float* __restrict__ W1,
                        const float* __restrict__ b1) {
    __shared__ float w1s[C1*C1];
    __shared__ float sS[C1], sQ[C1];
    int tid = threadIdx.x;
    for (int t = tid; t < C1*C1; t += blockDim.x) w1s[t] = W1[t];  // W1[o,0,h,0]
    if (tid < C1) { sS[tid] = 0.f; sQ[tid] = 0.f; }
    __syncthreads();

    int g = blockIdx.x * blockDim.x + tid;
    bool valid = (g < BS*WIN);
    int b = g / WIN, w = g % WIN;
    float xv[C1];
    if (valid) {
        #pragma unroll
        for (int h = 0; h < C1; h++) xv[h] = x[((size_t)b*C1 + h)*WIN + w];
    }
    for (int o = 0; o < C1; o++) {
        float acc = 0.f;
        if (valid) {
            acc = b1[o];
            #pragma unroll
            for (int h = 0; h < C1; h++) acc += xv[h] * w1s[o*C1 + h];
            g_h1[((size_t)b*C1 + o)*WIN + w] = acc;
        }
        float s = acc, q = acc*acc;
        #pragma unroll
        for (int d = 16; d; d >>= 1) {
            s += __shfl_xor_sync(0xffffffffu, s, d);
            q += __shfl_xor_sync(0xffffffffu, q, d);
        }
        if ((tid & 31) == 0) { atomicAdd(&sS[o], s); atomicAdd(&sQ[o], q); }
    }
    __syncthreads();
    if (tid < C1) {
        atomicAdd(&g_red[tid], sS[tid]);
        atomicAdd(&g_red[C1 + tid], sQ[tid]);
    }
}

__global__ void k_fin1(const float* __restrict__ g1, const float* __restrict__ be1) {
    int c = threadIdx.x;
    if (c >= C1) return;
    float cnt  = (float)((size_t)BS*WIN);
    float mean = g_red[c] / cnt;
    float var  = g_red[C1 + c] / cnt - mean*mean;
    float a = g1[c] * rsqrtf(var + 1e-5f);
    g_aff[c]      = a;
    g_aff[C1 + c] = be1[c] - mean*a;
}

// ------------------------------------------------------- conv2 + bn2 stats
#define CTILE 256
#define TPAD  267   // 256 + 11, odd stride (conflict-free)
__global__ __launch_bounds__(256) void k_conv2(const float* __restrict__ W2,
                                               const float* __restrict__ b2) {
    __shared__ float tile[C1*TPAD];     // 5874 floats
    __shared__ float w2s[C2*C1*KW];     // 5280 floats
    __shared__ float sS[C2], sQ[C2];
    int tid = threadIdx.x;
    int b  = blockIdx.y;
    int w0 = blockIdx.x * CTILE;

    for (int t = tid; t < C2*C1*KW; t += 256) w2s[t] = W2[t];
    if (tid < C2) { sS[tid] = 0.f; sQ[tid] = 0.f; }
    for (int t = tid; t < C1*TPAD; t += 256) {
        int i = t / TPAD, dw = t % TPAD;
        int gw = w0 - 6 + dw;
        float v = 0.f;
        if (gw >= 0 && gw < WIN)
            v = g_aff[i] * g_h1[((size_t)b*C1 + i)*WIN + gw] + g_aff[C1 + i];
        tile[t] = v;
    }
    __syncthreads();

    int o_grp = tid >> 6;        // 0..3 (warp-uniform)
    int widx  = tid & 63;
    int wl0   = widx * 4;

    float acc[20];
    #pragma unroll
    for (int oi = 0; oi < 5; oi++) {
        float bb = b2[o_grp*5 + oi];
        #pragma unroll
        for (int wj = 0; wj < 4; wj++) acc[oi*4 + wj] = bb;
    }
    for (int i = 0; i < C1; i++) {
        float tv[15];
        #pragma unroll
        for (int u = 0; u < 15; u++) tv[u] = tile[i*TPAD + wl0 + u];
        #pragma unroll
        for (int oi = 0; oi < 5; oi++) {
            int o = o_grp*5 + oi;
            #pragma unroll
            for (int k = 0; k < KW; k++) {
                float wv = w2s[(o*C1 + i)*KW + k];
                #pragma unroll
                for (int wj = 0; wj < 4; wj++) acc[oi*4 + wj] += tv[wj + k] * wv;
            }
        }
    }
    for (int oi = 0; oi < 5; oi++) {
        int o = o_grp*5 + oi;
        float s = 0.f, q = 0.f;
        #pragma unroll
        for (int wj = 0; wj < 4; wj++) {
            int w = w0 + wl0 + wj;
            if (w < W2L) {
                float v = acc[oi*4 + wj];
                g_h2[((size_t)b*C2 + o)*W2L + w] = v;
                s += v; q += v*v;
            }
        }
        #pragma unroll
        for (int d = 16; d; d >>= 1) {
            s += __shfl_xor_sync(0xffffffffu, s, d);
            q += __shfl_xor_sync(0xffffffffu, q, d);
        }
        if ((tid & 31) == 0) { atomicAdd(&sS[o], s); atomicAdd(&sQ[o], q); }
    }
    __syncthreads();
    if (tid < C2) {
        atomicAdd(&g_red[2*C1 + tid], sS[tid]);
        atomicAdd(&g_red[2*C1 + C2 + tid], sQ[tid]);
    }
}

__global__ void k_fin2(const float* __restrict__ g2, const float* __restrict__ be2) {
    int c = threadIdx.x;
    if (c >= C2) return;
    float cnt  = (float)((size_t)BS*W2L);
    float mean = g_red[2*C1 + c] / cnt;
    float var  = g_red[2*C1 + C2 + c] / cnt - mean*mean;
    float a = g2[c] * rsqrtf(var + 1e-5f);
    g_aff[2*C1 + c]      = a;
    g_aff[2*C1 + C2 + c] = be2[c] - mean*a;
}

// ----------------------------------------- covariance + Q/K/V congruence
#define SP 149   // row stride for sig (gcd(149,32)=1)
__global__ __launch_bounds__(192) void k_cov(const float* __restrict__ Wq,
                                             const float* __restrict__ Wk,
                                             const float* __restrict__ Wv) {
    __shared__ float sig[C2*SP];
    __shared__ float Cm[C2*C2];
    __shared__ float T[C2*NOUT];
    __shared__ float Ws[C2*NOUT];
    __shared__ float mean_s[C2];
    __shared__ float trs;
    const int offs[NEP] = {0, 147, 293};
    const int Ls[NEP]   = {147, 146, 146};
    int m = blockIdx.x, b = blockIdx.y;
    int off = offs[m], L = Ls[m];
    int tid = threadIdx.x;
    int warp = tid >> 5, lane = tid & 31;

    for (int t = tid; t < C2*L; t += 192) {
        int c = t / L, l = t % L;
        sig[c*SP + l] = g_aff[2*C1 + c] * g_h2[((size_t)b*C2 + c)*W2L + off + l]
                      + g_aff[2*C1 + C2 + c];
    }
    __syncthreads();
    for (int r = warp; r < C2; r += 6) {
        float s = 0.f;
        for (int l = lane; l < L; l += 32) s += sig[r*SP + l];
        #pragma unroll
        for (int d = 16; d; d >>= 1) s += __shfl_xor_sync(0xffffffffu, s, d);
        if (!lane) mean_s[r] = s / (float)L;
    }
    __syncthreads();
    for (int t = tid; t < C2*L; t += 192) sig[(t/L)*SP + (t%L)] -= mean_s[t/L];
    __syncthreads();
    for (int t = tid; t < 210; t += 192) {
        int p = 0, rem = t;
        while (rem >= C2 - p) { rem -= C2 - p; p++; }
        int q = p + rem;
        float s = 0.f;
        for (int l = 0; l < L; l++) s += sig[p*SP + l] * sig[q*SP + l];
        Cm[p*C2 + q] = s;
        Cm[q*C2 + p] = s;
    }
    __syncthreads();
    if (tid == 0) {
        float tr = 0.f;
        for (int i = 0; i < C2; i++) tr += Cm[i*C2 + i];
        trs = 1.f / tr;                    // (L-1) cancels in trace-normalization
    }
    __syncthreads();
    for (int t = tid; t < C2*C2; t += 192) {
        float v = Cm[t] * trs;
        if (t / C2 == t % C2) v += 1e-5f;
        Cm[t] = v;
    }
    __syncthreads();
    const float* Wp[3] = {Wq, Wk, Wv};
    for (int which = 0; which < 3; which++) {
        for (int t = tid; t < C2*NOUT; t += 192) Ws[t] = Wp[which][t];
        __syncthreads();
        for (int t = tid; t < C2*NOUT; t += 192) {
            int p = t / NOUT, j = t % NOUT;
            float s = 0.f;
            #pragma unroll
            for (int q = 0; q < C2; q++) s += Cm[p*C2 + q] * Ws[q*NOUT + j];
            T[t] = s;
        }
        __syncthreads();
        float* dst = &g_spd[((size_t)(b*NEP + m)*3 + which)*NOUT*NOUT];
        for (int t = tid; t < NOUT*NOUT; t += 192) {
            int i = t / NOUT, j = t % NOUT;
            float s = 0.f;
            #pragma unroll
            for (int p = 0; p < C2; p++) s += Ws[p*NOUT + i] * T[p*NOUT + j];
            dst[t] = s;
        }
        __syncthreads();
    }
}

// ------------------------------ warp-level parallel-round Jacobi (18x18)
// A, Vv: 18x18 in smem with row stride 19. cs/sn: 9 floats, pr/qr: 9 ints.
// PROVEN implementation (R8/R12 pass @ rel_err 9.6e-6).
__device__ __forceinline__ void warp_jacobi18(float* A, float* Vv,
                                              float* cs, float* sn,
                                              int* pr, int* qr,
                                              int lane, int nsweep) {
    #pragma unroll
    for (int it = 0; it < 11; it++) {
        int e = lane + 32*it;
        if (it < 10 || e < 324)
            Vv[(e/18)*19 + (e%18)] = (e/18 == e%18) ? 1.f : 0.f;
    }
    __syncwarp();

    // per-lane round-invariant item indices (162 items over 6 iterations)
    int piv[6], kkA[6], kkV[6];
    #pragma unroll
    for (int it = 0; it < 6; it++) {
        int t = lane + 32*it;
        if (t > 161) t = 161;                 // clamped lanes never store (va5 guard)
        piv[it] = t / 18;
        kkA[it] = t % 18;
        kkV[it] = (t % 18) * 19;
    }
    const bool va5 = (lane + 160) < 162;

    for (int sw = 0; sw < nsweep; sw++) {
        for (int r = 0; r < 17; r++) {
            if (lane < 9) {
                int a  = (lane == 0) ? 0 : (1 + ((lane - 1 + r) % 17));
                int jj = 17 - lane;
                int bb = 1 + ((jj - 1 + r) % 17);
                int p = a < bb ? a : bb;
                int q = a < bb ? bb : a;
                float app = A[p*19 + p], aqq = A[q*19 + q], apq = A[p*19 + q];
                float c = 1.f, s = 0.f;
                if (fabsf(apq) > 1e-36f) {
                    float tau = (aqq - app) / (2.f * apq);
                    float tt  = 1.f / (fabsf(tau) + sqrtf(1.f + tau*tau));
                    if (tau < 0.f) tt = -tt;
                    c = rsqrtf(1.f + tt*tt);
                    s = tt * c;
                }
                pr[lane] = p; qr[lane] = q; cs[lane] = c; sn[lane] = s;
            }
            __syncwarp();
            // fetch params once per round, keep for both phases
            int pR[6], qR[6]; float cR[6], sR[6];
            #pragma unroll
            for (int it = 0; it < 6; it++) {
                int pi = piv[it];
                pR[it] = pr[pi]; qR[it] = qr[pi];
                cR[it] = cs[pi]; sR[it] = sn[pi];
            }
            // phase 1: row rotations on A (J^T A) + column rotations on V (V J)
            #pragma unroll
            for (int it = 0; it < 6; it++) {
                if (it == 5 && !va5) break;
                int p = pR[it], q = qR[it];
                float c = cR[it], s = sR[it];
                float* Ap = &A[p*19]; float* Aq = &A[q*19];
                int k = kkA[it];
                float apk = Ap[k], aqk = Aq[k];
                Ap[k] = c*apk - s*aqk;
                Aq[k] = s*apk + c*aqk;
                float* Vk = &Vv[kkV[it]];
                float vkp = Vk[p], vkq = Vk[q];
                Vk[p] = c*vkp - s*vkq;
                Vk[q] = s*vkp + c*vkq;
            }
            __syncwarp();
            // phase 2: column rotations on A  ((J^T A) J)
            #pragma unroll
            for (int it = 0; it < 6; it++) {
                if (it == 5 && !va5) break;
                int p = pR[it], q = qR[it];
                float c = cR[it], s = sR[it];
                float* Ak = &A[kkV[it]];
                float akp = Ak[p], akq = Ak[q];
                Ak[p] = c*akp - s*akq;
                Ak[q] = s*akp + c*akq;
            }
            __syncwarp();
        }
    }
}

// --------------------------------------- eigh + log for all Q/K/V matrices
#define EW 768
__global__ __launch_bounds__(256) void k_eighlog() {
    __shared__ float sm[8*EW];
    int wid = threadIdx.x >> 5, lane = threadIdx.x & 31;
    size_t mat = (size_t)blockIdx.x * 8 + wid;
    float* A  = &sm[wid*EW];
    float* Vv = A + 342;
    float* ev = Vv + 342;
    float* cs = ev + 18;
    float* sn = cs + 9;
    int*   pr = (int*)(sn + 9);
    int*   qr = pr + 9;
    float* src = &g_spd[mat * 324];
    for (int e = lane; e < 324; e += 32) A[(e/18)*19 + (e%18)] = src[e];
    __syncwarp();
    warp_jacobi18(A, Vv, cs, sn, pr, qr, lane, NSWEEP);
    for (int k = lane; k < 18; k += 32) ev[k] = logf(fmaxf(A[k*19 + k], 1e-38f));
    __syncwarp();
    // pre-scale: A[i][k] = Vv[i][k] * ev[k]  (A dead; single FFMA per k below)
    for (int e = lane; e < 324; e += 32) {
        int i = e / 18, k = e % 18;
        A[i*19 + k] = Vv[i*19 + k] * ev[k];
    }
    __syncwarp();
    for (int e = lane; e < 324; e += 32) {
        int i = e / 18, j = e % 18;
        float s = 0.f;
        #pragma unroll
        for (int k = 0; k < 18; k++) s += A[i*19 + k] * Vv[j*19 + k];
        src[e] = s;  // overwrite with log-matrix
    }
}

// ------------- attention mix: energies, softmax, mix -> write into Q slots
__global__ __launch_bounds__(288) void k_attn_mix() {
    __shared__ float sLQ[3*324], sLK[3*324], sLV[3*324];
    __shared__ float sE[9], sP[9];
    int b = blockIdx.x, tid = threadIdx.x;
    int warp = tid >> 5, lane = tid & 31;
    size_t base = (size_t)b * 9 * 324;
    for (int t = tid; t < 3*324; t += 288) {
        int mm = t / 324, e = t % 324;
        sLQ[t] = g_spd[base + (mm*3 + 0)*324 + e];
        sLK[t] = g_spd[base + (mm*3 + 1)*324 + e];
        sLV[t] = g_spd[base + (mm*3 + 2)*324 + e];
    }
    __syncthreads();
    {   // 9 warps -> 9 (i,j) energy pairs
        int i = warp / 3, j = warp % 3;
        float s = 0.f;
        for (int e = lane; e < 324; e += 32) {
            float d = sLQ[i*324 + e] - sLK[j*324 + e];
            s += d*d;
        }
        #pragma unroll
        for (int d = 16; d; d >>= 1) s += __shfl_xor_sync(0xffffffffu, s, d);
        if (!lane) sE[i*3 + j] = s;
    }
    __syncthreads();
    if (tid < 3) {
        float sc[3]; float mx = -1e30f;
        #pragma unroll
        for (int j = 0; j < 3; j++) {
            sc[j] = 1.f / (1.f + log1pf(sE[tid*3 + j]));
            mx = fmaxf(mx, sc[j]);
        }
        float ss = 0.f;
        #pragma unroll
        for (int j = 0; j < 3; j++) { sc[j] = expf(sc[j] - mx); ss += sc[j]; }
        #pragma unroll
        for (int j = 0; j < 3; j++) sP[tid*3 + j] = sc[j] / ss;
    }
    __syncthreads();
    // mixed[j] = sum_i P[j,i] logV[i]  -> overwrite the (dead) logQ slot (j*3+0)
    for (int t = tid; t < 3*324; t += 288) {
        int j = t / 324, e = t % 324;
        float v = sP[j*3+0]*sLV[e] + sP[j*3+1]*sLV[324+e] + sP[j*3+2]*sLV[648+e];
        g_spd[base + (j*3 + 0)*324 + e] = v;
    }
}

// ------------- eigh(mixed) + rect-log + triu-vec (full 8-warp occupancy)
// identity: log(spd_rect(spd_exp(M), eps)) = U diag(max(s, log(eps))) U^T
__global__ __launch_bounds__(256) void k_eighfin() {
    __shared__ float sm[8*EW];
    int wid = threadIdx.x >> 5, lane = threadIdx.x & 31;
    int mat = blockIdx.x * 8 + wid;       // 0..6143: (b,m)
    int b = mat / 3, m = mat % 3;
    float* A  = &sm[wid*EW];
    float* Vv = A + 342;
    float* ev = Vv + 342;
    float* cs = ev + 18;
    float* sn = cs + 9;
    int*   pr = (int*)(sn + 9);
    int*   qr = pr + 9;
    const float* src = &g_spd[((size_t)b*9 + m*3 + 0)*324];
    for (int e = lane; e < 324; e += 32) A[(e/18)*19 + (e%18)] = src[e];
    __syncwarp();
    warp_jacobi18(A, Vv, cs, sn, pr, qr, lane, NSWEEP);
    for (int k = lane; k < 18; k += 32) ev[k] = fmaxf(A[k*19 + k], LN_RECT);
    __syncwarp();
    for (int e = lane; e < 324; e += 32) {
        int i = e / 18, k = e % 18;
        A[i*19 + k] = Vv[i*19 + k] * ev[k];
    }
    __syncwarp();
    for (int t = lane; t < 171; t += 32) {
        int i = 0, rem = t;
        while (rem >= 18 - i) { rem -= 18 - i; i++; }
        int j = i + rem;
        float s = 0.f;
        #pragma unroll
        for (int k = 0; k < 18; k++) s += A[i*19 + k] * Vv[j*19 + k];
        g_vec[(size_t)b*VECLEN + m*171 + t] = s;
    }
}

// ------------------------------------------------------------- output head
__global__ void k_out(const float* __restrict__ Wl, const float* __restrict__ bl,
                      float* __restrict__ out) {
    int g = blockIdx.x * blockDim.x + threadIdx.x;
    if (g >= BS*4) return;
    int b = g >> 2, j = g & 3;
    float s = bl[j];
    const float* v = &g_vec[(size_t)b*VECLEN];
    for (int t = 0; t < VECLEN; t++) s += v[t] * Wl[t*4 + j];
    out[g] = s;
}

// ---------------------------------------------------------------------------
extern "C" void kernel_launch(void* const* d_in, const int* in_sizes, int n_in,
                              void* d_out, int out_size) {
    const float* x   = (const float*)d_in[0];
    const float* W1  = (const float*)d_in[1];
    const float* b1  = (const float*)d_in[2];
    const float* g1  = (const float*)d_in[3];
    const float* be1 = (const float*)d_in[4];
    const float* W2  = (const float*)d_in[5];
    const float* b2  = (const float*)d_in[6];
    const float* g2  = (const float*)d_in[7];
    const float* be2 = (const float*)d_in[8];
    const float* Wq  = (const float*)d_in[9];
    const float* Wk  = (const float*)d_in[10];
    const float* Wv  = (const float*)d_in[11];
    const float* Wl  = (const float*)d_in[12];
    const float* bl  = (const float*)d_in[13];
    float* out = (float*)d_out;

    k_zero<<<1, 128>>>();
    k_conv1<<<(BS*WIN + 255)/256, 256>>>(x, W1, b1);
    k_fin1<<<1, 32>>>(g1, be1);
    k_conv2<<<dim3((W2L + CTILE - 1)/CTILE, BS), 256>>>(W2, b2);
    k_fin2<<<1, 32>>>(g2, be2);
    k_cov<<<dim3(NEP, BS), 192>>>(Wq, Wk, Wv);
    k_eighlog<<<NMATQKV/8, 256>>>();
    k_attn_mix<<<BS, 288>>>();
    k_eighfin<<<(BS*NEP)/8, 256>>>();
    k_out<<<(BS*4 + 255)/256, 256>>>(Wl, bl, out);
}

// round 15
// speedup vs baseline: 3.3713x; 1.1712x over previous
#include <cuda_runtime.h>
#include <math.h>

#define BS    2048
#define C1    22
#define WIN   438
#define C2    20
#define W2L   439
#define NIN   20
#define NOUT  18
#define NEP   3
#define KW    12
#define NMATQKV (BS*NEP*3)      // 18432 matrices (Q,K,V per (b,m))
#define VECLEN  513             // 3 * 171
#define LN_RECT (-9.2103403719761836f)  // log(1e-4)
#define NSWEEP  4

// ---------------- scratch (static device globals; no cudaMalloc allowed) ----
__device__ float g_h1[BS*C1*WIN];          // conv1 raw output
__device__ float g_h2[BS*C2*W2L];          // conv2 raw output
__device__ float g_spd[(size_t)NMATQKV*NOUT*NOUT];  // Q/K/V -> logm; Q slot reused for mixed
__device__ float g_vec[(size_t)BS*VECLEN];
__device__ float g_red[2*C1 + 2*C2];       // s1[22] q1[22] s2[20] q2[20]
__device__ float g_aff[2*C1 + 2*C2];       // a1[22] c1[22] a2[20] c2[20]

// ---------------------------------------------------------------- zero stats
__global__ void k_zero() {
    int t = threadIdx.x;
    if (t < 2*C1 + 2*C2) g_red[t] = 0.f;
}

// ------------------------------------------------------- conv1 + bn1 stats
__global__ void k_conv1(const float* __restrict__ x,
                        const float* __restrict__ W1,
                        const float* __restrict__ b1) {
    __shared__ float w1s[C1*C1];
    __shared__ float sS[C1], sQ[C1];
    int tid = threadIdx.x;
    for (int t = tid; t < C1*C1; t += blockDim.x) w1s[t] = W1[t];  // W1[o,0,h,0]
    if (tid < C1) { sS[tid] = 0.f; sQ[tid] = 0.f; }
    __syncthreads();

    int g = blockIdx.x * blockDim.x + tid;
    bool valid = (g < BS*WIN);
    int b = g / WIN, w = g % WIN;
    float xv[C1];
    if (valid) {
        #pragma unroll
        for (int h = 0; h < C1; h++) xv[h] = x[((size_t)b*C1 + h)*WIN + w];
    }
    for (int o = 0; o < C1; o++) {
        float acc = 0.f;
        if (valid) {
            acc = b1[o];
            #pragma unroll
            for (int h = 0; h < C1; h++) acc += xv[h] * w1s[o*C1 + h];
            g_h1[((size_t)b*C1 + o)*WIN + w] = acc;
        }
        float s = acc, q = acc*acc;
        #pragma unroll
        for (int d = 16; d; d >>= 1) {
            s += __shfl_xor_sync(0xffffffffu, s, d);
            q += __shfl_xor_sync(0xffffffffu, q, d);
        }
        if ((tid & 31) == 0) { atomicAdd(&sS[o], s); atomicAdd(&sQ[o], q); }
    }
    __syncthreads();
    if (tid < C1) {
        atomicAdd(&g_red[tid], sS[tid]);
        atomicAdd(&g_red[C1 + tid], sQ[tid]);
    }
}

__global__ void k_fin1(const float* __restrict__ g1, const float* __restrict__ be1) {
    int c = threadIdx.x;
    if (c >= C1) return;
    float cnt  = (float)((size_t)BS*WIN);
    float mean = g_red[c] / cnt;
    float var  = g_red[C1 + c] / cnt - mean*mean;
    float a = g1[c] * rsqrtf(var + 1e-5f);
    g_aff[c]      = a;
    g_aff[C1 + c] = be1[c] - mean*a;
}

// ------------------------------------------------------- conv2 + bn2 stats
#define CTILE 256
#define TPAD  267   // 256 + 11, odd stride (conflict-free)
__global__ __launch_bounds__(256) void k_conv2(const float* __restrict__ W2,
                                               const float* __restrict__ b2) {
    __shared__ float tile[C1*TPAD];     // 5874 floats
    __shared__ float w2s[C2*C1*KW];     // 5280 floats
    __shared__ float sS[C2], sQ[C2];
    int tid = threadIdx.x;
    int b  = blockIdx.y;
    int w0 = blockIdx.x * CTILE;

    for (int t = tid; t < C2*C1*KW; t += 256) w2s[t] = W2[t];
    if (tid < C2) { sS[tid] = 0.f; sQ[tid] = 0.f; }
    for (int t = tid; t < C1*TPAD; t += 256) {
        int i = t / TPAD, dw = t % TPAD;
        int gw = w0 - 6 + dw;
        float v = 0.f;
        if (gw >= 0 && gw < WIN)
            v = g_aff[i] * g_h1[((size_t)b*C1 + i)*WIN + gw] + g_aff[C1 + i];
        tile[t] = v;
    }
    __syncthreads();

    int o_grp = tid >> 6;        // 0..3 (warp-uniform)
    int widx  = tid & 63;
    int wl0   = widx * 4;

    float acc[20];
    #pragma unroll
    for (int oi = 0; oi < 5; oi++) {
        float bb = b2[o_grp*5 + oi];
        #pragma unroll
        for (int wj = 0; wj < 4; wj++) acc[oi*4 + wj] = bb;
    }
    for (int i = 0; i < C1; i++) {
        float tv[15];
        #pragma unroll
        for (int u = 0; u < 15; u++) tv[u] = tile[i*TPAD + wl0 + u];
        #pragma unroll
        for (int oi = 0; oi < 5; oi++) {
            int o = o_grp*5 + oi;
            #pragma unroll
            for (int k = 0; k < KW; k++) {
                float wv = w2s[(o*C1 + i)*KW + k];
                #pragma unroll
                for (int wj = 0; wj < 4; wj++) acc[oi*4 + wj] += tv[wj + k] * wv;
            }
        }
    }
    for (int oi = 0; oi < 5; oi++) {
        int o = o_grp*5 + oi;
        float s = 0.f, q = 0.f;
        #pragma unroll
        for (int wj = 0; wj < 4; wj++) {
            int w = w0 + wl0 + wj;
            if (w < W2L) {
                float v = acc[oi*4 + wj];
                g_h2[((size_t)b*C2 + o)*W2L + w] = v;
                s += v; q += v*v;
            }
        }
        #pragma unroll
        for (int d = 16; d; d >>= 1) {
            s += __shfl_xor_sync(0xffffffffu, s, d);
            q += __shfl_xor_sync(0xffffffffu, q, d);
        }
        if ((tid & 31) == 0) { atomicAdd(&sS[o], s); atomicAdd(&sQ[o], q); }
    }
    __syncthreads();
    if (tid < C2) {
        atomicAdd(&g_red[2*C1 + tid], sS[tid]);
        atomicAdd(&g_red[2*C1 + C2 + tid], sQ[tid]);
    }
}

__global__ void k_fin2(const float* __restrict__ g2, const float* __restrict__ be2) {
    int c = threadIdx.x;
    if (c >= C2) return;
    float cnt  = (float)((size_t)BS*W2L);
    float mean = g_red[2*C1 + c] / cnt;
    float var  = g_red[2*C1 + C2 + c] / cnt - mean*mean;
    float a = g2[c] * rsqrtf(var + 1e-5f);
    g_aff[2*C1 + c]      = a;
    g_aff[2*C1 + C2 + c] = be2[c] - mean*a;
}

// ----------------------------------------- covariance + Q/K/V congruence
#define SP 149   // row stride for sig (gcd(149,32)=1)
__global__ __launch_bounds__(192) void k_cov(const float* __restrict__ Wq,
                                             const float* __restrict__ Wk,
                                             const float* __restrict__ Wv) {
    __shared__ float sig[C2*SP];
    __shared__ float Cm[C2*C2];
    __shared__ float T[C2*NOUT];
    __shared__ float Ws[C2*NOUT];
    __shared__ float mean_s[C2];
    __shared__ float trs;
    const int offs[NEP] = {0, 147, 293};
    const int Ls[NEP]   = {147, 146, 146};
    int m = blockIdx.x, b = blockIdx.y;
    int off = offs[m], L = Ls[m];
    int tid = threadIdx.x;
    int warp = tid >> 5, lane = tid & 31;

    for (int t = tid; t < C2*L; t += 192) {
        int c = t / L, l = t % L;
        sig[c*SP + l] = g_aff[2*C1 + c] * g_h2[((size_t)b*C2 + c)*W2L + off + l]
                      + g_aff[2*C1 + C2 + c];
    }
    __syncthreads();
    for (int r = warp; r < C2; r += 6) {
        float s = 0.f;
        for (int l = lane; l < L; l += 32) s += sig[r*SP + l];
        #pragma unroll
        for (int d = 16; d; d >>= 1) s += __shfl_xor_sync(0xffffffffu, s, d);
        if (!lane) mean_s[r] = s / (float)L;
    }
    __syncthreads();
    for (int t = tid; t < C2*L; t += 192) sig[(t/L)*SP + (t%L)] -= mean_s[t/L];
    __syncthreads();
    for (int t = tid; t < 210; t += 192) {
        int p = 0, rem = t;
        while (rem >= C2 - p) { rem -= C2 - p; p++; }
        int q = p + rem;
        float s = 0.f;
        for (int l = 0; l < L; l++) s += sig[p*SP + l] * sig[q*SP + l];
        Cm[p*C2 + q] = s;
        Cm[q*C2 + p] = s;
    }
    __syncthreads();
    if (tid == 0) {
        float tr = 0.f;
        for (int i = 0; i < C2; i++) tr += Cm[i*C2 + i];
        trs = 1.f / tr;                    // (L-1) cancels in trace-normalization
    }
    __syncthreads();
    for (int t = tid; t < C2*C2; t += 192) {
        float v = Cm[t] * trs;
        if (t / C2 == t % C2) v += 1e-5f;
        Cm[t] = v;
    }
    __syncthreads();
    const float* Wp[3] = {Wq, Wk, Wv};
    for (int which = 0; which < 3; which++) {
        for (int t = tid; t < C2*NOUT; t += 192) Ws[t] = Wp[which][t];
        __syncthreads();
        for (int t = tid; t < C2*NOUT; t += 192) {
            int p = t / NOUT, j = t % NOUT;
            float s = 0.f;
            #pragma unroll
            for (int q = 0; q < C2; q++) s += Cm[p*C2 + q] * Ws[q*NOUT + j];
            T[t] = s;
        }
        __syncthreads();
        float* dst = &g_spd[((size_t)(b*NEP + m)*3 + which)*NOUT*NOUT];
        for (int t = tid; t < NOUT*NOUT; t += 192) {
            int i = t / NOUT, j = t % NOUT;
            float s = 0.f;
            #pragma unroll
            for (int p = 0; p < C2; p++) s += Ws[p*NOUT + i] * T[p*NOUT + j];
            dst[t] = s;
        }
        __syncthreads();
    }
}

// ------------------------------ warp-level parallel-round Jacobi (18x18)
// A, Vv: 18x18 in smem with row stride 19.
// v2: fused 2x2-block similarity update (one A read+write per element per
// round instead of two) + rotation params broadcast via shfl (no smem).
// The 9 disjoint rotations partition A into 81 independent 2x2 blocks:
//   B' = Ri^T B Rj,  Ri = [[c,s],[-s,c]] on (pI,qI), Rj likewise on (pJ,qJ).
// Fused intermediates (t = Ri^T B; B' = t Rj) are identical to the proven
// two-phase code's values -> numerics unchanged.
__device__ __forceinline__ void warp_jacobi18(float* A, float* Vv,
                                              int lane, int nsweep) {
    #pragma unroll
    for (int it = 0; it < 11; it++) {
        int e = lane + 32*it;
        if (it < 10 || e < 324)
            Vv[(e/18)*19 + (e%18)] = (e/18 == e%18) ? 1.f : 0.f;
    }
    // V item indices (162 items over 6 iterations) — round-invariant
    int piv[6], kkV[6];
    #pragma unroll
    for (int it = 0; it < 6; it++) {
        int t = lane + 32*it;
        if (t > 161) t = 161;                 // clamped lanes never store
        piv[it] = t / 18;
        kkV[it] = (t % 18) * 19;
    }
    const bool vva5 = (lane + 160) < 162;
    // A block indices (81 blocks over 3 iterations) — round-invariant
    int bi[3], bj[3];
    #pragma unroll
    for (int it = 0; it < 3; it++) {
        int bb = lane + 32*it;
        if (bb > 80) bb = 80;                 // clamped lanes never store
        bi[it] = bb / 9;
        bj[it] = bb % 9;
    }
    const bool ba2 = (lane + 64) < 81;
    __syncwarp();

    for (int sw = 0; sw < nsweep; sw++) {
        for (int r = 0; r < 17; r++) {
            // pivot: lane i (i<9) owns pair i of this round (regs, no smem)
            float c_ = 1.f, s_ = 0.f; int ppq_ = 0;
            if (lane < 9) {
                int a   = (lane == 0) ? 0 : (1 + ((lane - 1 + r) % 17));
                int jj  = 17 - lane;
                int bb2 = 1 + ((jj - 1 + r) % 17);
                int p = a < bb2 ? a : bb2;
                int q = a < bb2 ? bb2 : a;
                float app = A[p*19 + p], aqq = A[q*19 + q], apq = A[p*19 + q];
                if (fabsf(apq) > 1e-36f) {
                    float tau = (aqq - app) / (2.f * apq);
                    float tt  = 1.f / (fabsf(tau) + sqrtf(1.f + tau*tau));
                    if (tau < 0.f) tt = -tt;
                    c_ = rsqrtf(1.f + tt*tt);
                    s_ = tt * c_;
                }
                ppq_ = (p << 5) | q;
            }
            __syncwarp();   // pivot reads of A complete before block writes
            // fused A block updates: B' = Ri^T B Rj  (blocks fully disjoint)
            #pragma unroll
            for (int it = 0; it < 3; it++) {
                int i = bi[it], j = bj[it];
                int   pqI = __shfl_sync(0xffffffffu, ppq_, i);
                int   pqJ = __shfl_sync(0xffffffffu, ppq_, j);
                float ci  = __shfl_sync(0xffffffffu, c_, i);
                float si  = __shfl_sync(0xffffffffu, s_, i);
                float cj  = __shfl_sync(0xffffffffu, c_, j);
                float sj  = __shfl_sync(0xffffffffu, s_, j);
                if (it == 2 && !ba2) continue;
                int pI = pqI >> 5, qI = pqI & 31;
                int pJ = pqJ >> 5, qJ = pqJ & 31;
                float* Ap = &A[pI*19]; float* Aq = &A[qI*19];
                float b00 = Ap[pJ], b01 = Ap[qJ];
                float b10 = Aq[pJ], b11 = Aq[qJ];
                float t00 = ci*b00 - si*b10, t01 = ci*b01 - si*b11;
                float t10 = si*b00 + ci*b10, t11 = si*b01 + ci*b11;
                Ap[pJ] = cj*t00 - sj*t01;
                Ap[qJ] = sj*t00 + cj*t01;
                Aq[pJ] = cj*t10 - sj*t11;
                Aq[qJ] = sj*t10 + cj*t11;
            }
            // V column rotations (V J)
            #pragma unroll
            for (int it = 0; it < 6; it++) {
                int pi2 = piv[it];
                int   pq = __shfl_sync(0xffffffffu, ppq_, pi2);
                float ci = __shfl_sync(0xffffffffu, c_, pi2);
                float si = __shfl_sync(0xffffffffu, s_, pi2);
                if (it == 5 && !vva5) continue;
                int p = pq >> 5, q = pq & 31;
                float* Vk = &Vv[kkV[it]];
                float vkp = Vk[p], vkq = Vk[q];
                Vk[p] = ci*vkp - si*vkq;
                Vk[q] = si*vkp + ci*vkq;
            }
            __syncwarp();   // writes visible to next round's pivot
        }
    }
}

// --------------------------------------- eigh + log for all Q/K/V matrices
#define EW 768
__global__ __launch_bounds__(256) void k_eighlog() {
    __shared__ float sm[8*EW];
    int wid = threadIdx.x >> 5, lane = threadIdx.x & 31;
    size_t mat = (size_t)blockIdx.x * 8 + wid;
    float* A  = &sm[wid*EW];
    float* Vv = A + 342;
    float* ev = Vv + 342;
    float* src = &g_spd[mat * 324];
    for (int e = lane; e < 324; e += 32) A[(e/18)*19 + (e%18)] = src[e];
    __syncwarp();
    warp_jacobi18(A, Vv, lane, NSWEEP);
    for (int k = lane; k < 18; k += 32) ev[k] = logf(fmaxf(A[k*19 + k], 1e-38f));
    __syncwarp();
    // pre-scale: A[i][k] = Vv[i][k] * ev[k]  (A dead; single FFMA per k below)
    for (int e = lane; e < 324; e += 32) {
        int i = e / 18, k = e % 18;
        A[i*19 + k] = Vv[i*19 + k] * ev[k];
    }
    __syncwarp();
    for (int e = lane; e < 324; e += 32) {
        int i = e / 18, j = e % 18;
        float s = 0.f;
        #pragma unroll
        for (int k = 0; k < 18; k++) s += A[i*19 + k] * Vv[j*19 + k];
        src[e] = s;  // overwrite with log-matrix
    }
}

// ------------- attention mix: energies, softmax, mix -> write into Q slots
__global__ __launch_bounds__(288) void k_attn_mix() {
    __shared__ float sLQ[3*324], sLK[3*324], sLV[3*324];
    __shared__ float sE[9], sP[9];
    int b = blockIdx.x, tid = threadIdx.x;
    int warp = tid >> 5, lane = tid & 31;
    size_t base = (size_t)b * 9 * 324;
    for (int t = tid; t < 3*324; t += 288) {
        int mm = t / 324, e = t % 324;
        sLQ[t] = g_spd[base + (mm*3 + 0)*324 + e];
        sLK[t] = g_spd[base + (mm*3 + 1)*324 + e];
        sLV[t] = g_spd[base + (mm*3 + 2)*324 + e];
    }
    __syncthreads();
    {   // 9 warps -> 9 (i,j) energy pairs
        int i = warp / 3, j = warp % 3;
        float s = 0.f;
        for (int e = lane; e < 324; e += 32) {
            float d = sLQ[i*324 + e] - sLK[j*324 + e];
            s += d*d;
        }
        #pragma unroll
        for (int d = 16; d; d >>= 1) s += __shfl_xor_sync(0xffffffffu, s, d);
        if (!lane) sE[i*3 + j] = s;
    }
    __syncthreads();
    if (tid < 3) {
        float sc[3]; float mx = -1e30f;
        #pragma unroll
        for (int j = 0; j < 3; j++) {
            sc[j] = 1.f / (1.f + log1pf(sE[tid*3 + j]));
            mx = fmaxf(mx, sc[j]);
        }
        float ss = 0.f;
        #pragma unroll
        for (int j = 0; j < 3; j++) { sc[j] = expf(sc[j] - mx); ss += sc[j]; }
        #pragma unroll
        for (int j = 0; j < 3; j++) sP[tid*3 + j] = sc[j] / ss;
    }
    __syncthreads();
    // mixed[j] = sum_i P[j,i] logV[i]  -> overwrite the (dead) logQ slot (j*3+0)
    for (int t = tid; t < 3*324; t += 288) {
        int j = t / 324, e = t % 324;
        float v = sP[j*3+0]*sLV[e] + sP[j*3+1]*sLV[324+e] + sP[j*3+2]*sLV[648+e];
        g_spd[base + (j*3 + 0)*324 + e] = v;
    }
}

// ------------- eigh(mixed) + rect-log + triu-vec (full 8-warp occupancy)
// identity: log(spd_rect(spd_exp(M), eps)) = U diag(max(s, log(eps))) U^T
__global__ __launch_bounds__(256) void k_eighfin() {
    __shared__ float sm[8*EW];
    int wid = threadIdx.x >> 5, lane = threadIdx.x & 31;
    int mat = blockIdx.x * 8 + wid;       // 0..6143: (b,m)
    int b = mat / 3, m = mat % 3;
    float* A  = &sm[wid*EW];
    float* Vv = A + 342;
    float* ev = Vv + 342;
    const float* src = &g_spd[((size_t)b*9 + m*3 + 0)*324];
    for (int e = lane; e < 324; e += 32) A[(e/18)*19 + (e%18)] = src[e];
    __syncwarp();
    warp_jacobi18(A, Vv, lane, NSWEEP);
    for (int k = lane; k < 18; k += 32) ev[k] = fmaxf(A[k*19 + k], LN_RECT);
    __syncwarp();
    for (int e = lane; e < 324; e += 32) {
        int i = e / 18, k = e % 18;
        A[i*19 + k] = Vv[i*19 + k] * ev[k];
    }
    __syncwarp();
    for (int t = lane; t < 171; t += 32) {
        int i = 0, rem = t;
        while (rem >= 18 - i) { rem -= 18 - i; i++; }
        int j = i + rem;
        float s = 0.f;
        #pragma unroll
        for (int k = 0; k < 18; k++) s += A[i*19 + k] * Vv[j*19 + k];
        g_vec[(size_t)b*VECLEN + m*171 + t] = s;
    }
}

// ------------------------------------------------------------- output head
__global__ void k_out(const float* __restrict__ Wl, const float* __restrict__ bl,
                      float* __restrict__ out) {
    int g = blockIdx.x * blockDim.x + threadIdx.x;
    if (g >= BS*4) return;
    int b = g >> 2, j = g & 3;
    float s = bl[j];
    const float* v = &g_vec[(size_t)b*VECLEN];
    for (int t = 0; t < VECLEN; t++) s += v[t] * Wl[t*4 + j];
    out[g] = s;
}

// ---------------------------------------------------------------------------
extern "C" void kernel_launch(void* const* d_in, const int* in_sizes, int n_in,
                              void* d_out, int out_size) {
    const float* x   = (const float*)d_in[0];
    const float* W1  = (const float*)d_in[1];
    const float* b1  = (const float*)d_in[2];
    const float* g1  = (const float*)d_in[3];
    const float* be1 = (const float*)d_in[4];
    const float* W2  = (const float*)d_in[5];
    const float* b2  = (const float*)d_in[6];
    const float* g2  = (const float*)d_in[7];
    const float* be2 = (const float*)d_in[8];
    const float* Wq  = (const float*)d_in[9];
    const float* Wk  = (const float*)d_in[10];
    const float* Wv  = (const float*)d_in[11];
    const float* Wl  = (const float*)d_in[12];
    const float* bl  = (const float*)d_in[13];
    float* out = (float*)d_out;

    k_zero<<<1, 128>>>();
    k_conv1<<<(BS*WIN + 255)/256, 256>>>(x, W1, b1);
    k_fin1<<<1, 32>>>(g1, be1);
    k_conv2<<<dim3((W2L + CTILE - 1)/CTILE, BS), 256>>>(W2, b2);
    k_fin2<<<1, 32>>>(g2, be2);
    k_cov<<<dim3(NEP, BS), 192>>>(Wq, Wk, Wv);
    k_eighlog<<<NMATQKV/8, 256>>>();
    k_attn_mix<<<BS, 288>>>();
    k_eighfin<<<(BS*NEP)/8, 256>>>();
    k_out<<<(BS*4 + 255)/256, 256>>>(Wl, bl, out);
}

// round 16
// speedup vs baseline: 3.5205x; 1.0442x over previous
#include <cuda_runtime.h>
#include <math.h>

#define BS    2048
#define C1    22
#define WIN   438
#define C2    20
#define W2L   439
#define NIN   20
#define NOUT  18
#define NEP   3
#define KW    12
#define NMATQKV (BS*NEP*3)      // 18432 matrices (Q,K,V per (b,m))
#define VECLEN  513             // 3 * 171
#define LN_RECT (-9.2103403719761836f)  // log(1e-4)
#define NSWEEP  4

// ---------------- scratch (static device globals; no cudaMalloc allowed) ----
__device__ float g_h1[BS*C1*WIN];          // conv1 raw output
__device__ float g_h2[BS*C2*W2L];          // conv2 raw output
__device__ float g_spd[(size_t)NMATQKV*NOUT*NOUT];  // Q/K/V -> logm; Q slot reused for mixed
__device__ float g_vec[(size_t)BS*VECLEN];
__device__ float g_red[2*C1 + 2*C2];       // s1[22] q1[22] s2[20] q2[20]
__device__ float g_aff[2*C1 + 2*C2];       // a1[22] c1[22] a2[20] c2[20]

// ---------------------------------------------------------------- zero stats
__global__ void k_zero() {
    int t = threadIdx.x;
    if (t < 2*C1 + 2*C2) g_red[t] = 0.f;
}

// ------------------------------------------------------- conv1 + bn1 stats
__global__ void k_conv1(const float* __restrict__ x,
                        const float* __restrict__ W1,
                        const float* __restrict__ b1) {
    __shared__ float w1s[C1*C1];
    __shared__ float sS[C1], sQ[C1];
    int tid = threadIdx.x;
    for (int t = tid; t < C1*C1; t += blockDim.x) w1s[t] = W1[t];  // W1[o,0,h,0]
    if (tid < C1) { sS[tid] = 0.f; sQ[tid] = 0.f; }
    __syncthreads();

    int g = blockIdx.x * blockDim.x + tid;
    bool valid = (g < BS*WIN);
    int b = g / WIN, w = g % WIN;
    float xv[C1];
    if (valid) {
        #pragma unroll
        for (int h = 0; h < C1; h++) xv[h] = x[((size_t)b*C1 + h)*WIN + w];
    }
    for (int o = 0; o < C1; o++) {
        float acc = 0.f;
        if (valid) {
            acc = b1[o];
            #pragma unroll
            for (int h = 0; h < C1; h++) acc += xv[h] * w1s[o*C1 + h];
            g_h1[((size_t)b*C1 + o)*WIN + w] = acc;
        }
        float s = acc, q = acc*acc;
        #pragma unroll
        for (int d = 16; d; d >>= 1) {
            s += __shfl_xor_sync(0xffffffffu, s, d);
            q += __shfl_xor_sync(0xffffffffu, q, d);
        }
        if ((tid & 31) == 0) { atomicAdd(&sS[o], s); atomicAdd(&sQ[o], q); }
    }
    __syncthreads();
    if (tid < C1) {
        atomicAdd(&g_red[tid], sS[tid]);
        atomicAdd(&g_red[C1 + tid], sQ[tid]);
    }
}

__global__ void k_fin1(const float* __restrict__ g1, const float* __restrict__ be1) {
    int c = threadIdx.x;
    if (c >= C1) return;
    float cnt  = (float)((size_t)BS*WIN);
    float mean = g_red[c] / cnt;
    float var  = g_red[C1 + c] / cnt - mean*mean;
    float a = g1[c] * rsqrtf(var + 1e-5f);
    g_aff[c]      = a;
    g_aff[C1 + c] = be1[c] - mean*a;
}

// ------------------------------------------------------- conv2 + bn2 stats
#define CTILE 256
#define TPAD  268   // 256 + 12; rows 16B-aligned (268*4=1072=67*16) for float4
__global__ __launch_bounds__(256) void k_conv2(const float* __restrict__ W2,
                                               const float* __restrict__ b2) {
    __shared__ __align__(16) float tile[C1*TPAD];   // 5896 floats
    __shared__ __align__(16) float w2s[C2*C1*KW];   // 5280 floats
    __shared__ float sS[C2], sQ[C2];
    int tid = threadIdx.x;
    int b  = blockIdx.y;
    int w0 = blockIdx.x * CTILE;

    for (int t = tid; t < C2*C1*KW; t += 256) w2s[t] = W2[t];
    if (tid < C2) { sS[tid] = 0.f; sQ[tid] = 0.f; }
    for (int t = tid; t < C1*TPAD; t += 256) {
        int i = t / TPAD, dw = t % TPAD;
        int gw = w0 - 6 + dw;
        float v = 0.f;
        if (gw >= 0 && gw < WIN)
            v = g_aff[i] * g_h1[((size_t)b*C1 + i)*WIN + gw] + g_aff[C1 + i];
        tile[t] = v;
    }
    __syncthreads();

    int o_grp = tid >> 6;        // 0..3 (warp-uniform)
    int widx  = tid & 63;
    int wl0   = widx * 4;

    float acc[20];
    #pragma unroll
    for (int oi = 0; oi < 5; oi++) {
        float bb = b2[o_grp*5 + oi];
        #pragma unroll
        for (int wj = 0; wj < 4; wj++) acc[oi*4 + wj] = bb;
    }
    for (int i = 0; i < C1; i++) {
        // 16 floats via 4 LDS.128 (conflict-free: 16B lane stride), use 15
        float4 t0 = *(const float4*)&tile[i*TPAD + wl0];
        float4 t1 = *(const float4*)&tile[i*TPAD + wl0 + 4];
        float4 t2 = *(const float4*)&tile[i*TPAD + wl0 + 8];
        float4 t3 = *(const float4*)&tile[i*TPAD + wl0 + 12];
        float tv[15] = {t0.x, t0.y, t0.z, t0.w,
                        t1.x, t1.y, t1.z, t1.w,
                        t2.x, t2.y, t2.z, t2.w,
                        t3.x, t3.y, t3.z};
        #pragma unroll
        for (int oi = 0; oi < 5; oi++) {
            int o = o_grp*5 + oi;
            // 12 contiguous weights via 3 uniform LDS.128
            const float4* wp = (const float4*)&w2s[(o*C1 + i)*KW];
            float4 wa = wp[0], wb = wp[1], wc = wp[2];
            float wk[12] = {wa.x, wa.y, wa.z, wa.w,
                            wb.x, wb.y, wb.z, wb.w,
                            wc.x, wc.y, wc.z, wc.w};
            #pragma unroll
            for (int k = 0; k < KW; k++) {
                float wv = wk[k];
                #pragma unroll
                for (int wj = 0; wj < 4; wj++) acc[oi*4 + wj] += tv[wj + k] * wv;
            }
        }
    }
    for (int oi = 0; oi < 5; oi++) {
        int o = o_grp*5 + oi;
        float s = 0.f, q = 0.f;
        #pragma unroll
        for (int wj = 0; wj < 4; wj++) {
            int w = w0 + wl0 + wj;
            if (w < W2L) {
                float v = acc[oi*4 + wj];
                g_h2[((size_t)b*C2 + o)*W2L + w] = v;
                s += v; q += v*v;
            }
        }
        #pragma unroll
        for (int d = 16; d; d >>= 1) {
            s += __shfl_xor_sync(0xffffffffu, s, d);
            q += __shfl_xor_sync(0xffffffffu, q, d);
        }
        if ((tid & 31) == 0) { atomicAdd(&sS[o], s); atomicAdd(&sQ[o], q); }
    }
    __syncthreads();
    if (tid < C2) {
        atomicAdd(&g_red[2*C1 + tid], sS[tid]);
        atomicAdd(&g_red[2*C1 + C2 + tid], sQ[tid]);
    }
}

__global__ void k_fin2(const float* __restrict__ g2, const float* __restrict__ be2) {
    int c = threadIdx.x;
    if (c >= C2) return;
    float cnt  = (float)((size_t)BS*W2L);
    float mean = g_red[2*C1 + c] / cnt;
    float var  = g_red[2*C1 + C2 + c] / cnt - mean*mean;
    float a = g2[c] * rsqrtf(var + 1e-5f);
    g_aff[2*C1 + c]      = a;
    g_aff[2*C1 + C2 + c] = be2[c] - mean*a;
}

// ----------------------------------------- covariance + Q/K/V congruence
#define SP 149   // row stride for sig (gcd(149,32)=1)
__global__ __launch_bounds__(192) void k_cov(const float* __restrict__ Wq,
                                             const float* __restrict__ Wk,
                                             const float* __restrict__ Wv) {
    __shared__ float sig[C2*SP];
    __shared__ float Cm[C2*C2];
    __shared__ float T[C2*NOUT];
    __shared__ float Ws[C2*NOUT];
    __shared__ float mean_s[C2];
    __shared__ float trs;
    const int offs[NEP] = {0, 147, 293};
    const int Ls[NEP]   = {147, 146, 146};
    int m = blockIdx.x, b = blockIdx.y;
    int off = offs[m], L = Ls[m];
    int tid = threadIdx.x;
    int warp = tid >> 5, lane = tid & 31;

    for (int t = tid; t < C2*L; t += 192) {
        int c = t / L, l = t % L;
        sig[c*SP + l] = g_aff[2*C1 + c] * g_h2[((size_t)b*C2 + c)*W2L + off + l]
                      + g_aff[2*C1 + C2 + c];
    }
    __syncthreads();
    for (int r = warp; r < C2; r += 6) {
        float s = 0.f;
        for (int l = lane; l < L; l += 32) s += sig[r*SP + l];
        #pragma unroll
        for (int d = 16; d; d >>= 1) s += __shfl_xor_sync(0xffffffffu, s, d);
        if (!lane) mean_s[r] = s / (float)L;
    }
    __syncthreads();
    for (int t = tid; t < C2*L; t += 192) sig[(t/L)*SP + (t%L)] -= mean_s[t/L];
    __syncthreads();
    for (int t = tid; t < 210; t += 192) {
        int p = 0, rem = t;
        while (rem >= C2 - p) { rem -= C2 - p; p++; }
        int q = p + rem;
        float s = 0.f;
        for (int l = 0; l < L; l++) s += sig[p*SP + l] * sig[q*SP + l];
        Cm[p*C2 + q] = s;
        Cm[q*C2 + p] = s;
    }
    __syncthreads();
    if (tid == 0) {
        float tr = 0.f;
        for (int i = 0; i < C2; i++) tr += Cm[i*C2 + i];
        trs = 1.f / tr;                    // (L-1) cancels in trace-normalization
    }
    __syncthreads();
    for (int t = tid; t < C2*C2; t += 192) {
        float v = Cm[t] * trs;
        if (t / C2 == t % C2) v += 1e-5f;
        Cm[t] = v;
    }
    __syncthreads();
    const float* Wp[3] = {Wq, Wk, Wv};
    for (int which = 0; which < 3; which++) {
        for (int t = tid; t < C2*NOUT; t += 192) Ws[t] = Wp[which][t];
        __syncthreads();
        for (int t = tid; t < C2*NOUT; t += 192) {
            int p = t / NOUT, j = t % NOUT;
            float s = 0.f;
            #pragma unroll
            for (int q = 0; q < C2; q++) s += Cm[p*C2 + q] * Ws[q*NOUT + j];
            T[t] = s;
        }
        __syncthreads();
        float* dst = &g_spd[((size_t)(b*NEP + m)*3 + which)*NOUT*NOUT];
        for (int t = tid; t < NOUT*NOUT; t += 192) {
            int i = t / NOUT, j = t % NOUT;
            float s = 0.f;
            #pragma unroll
            for (int p = 0; p < C2; p++) s += Ws[p*NOUT + i] * T[p*NOUT + j];
            dst[t] = s;
        }
        __syncthreads();
    }
}

// ------------------------------ warp-level parallel-round Jacobi (18x18)
// A, Vv: 18x18 in smem with row stride 19.
// Fused 2x2-block similarity update + shfl-broadcast rotation params.
// PROVEN (R15 pass @ rel_err 2.015e-4).
__device__ __forceinline__ void warp_jacobi18(float* A, float* Vv,
                                              int lane, int nsweep) {
    #pragma unroll
    for (int it = 0; it < 11; it++) {
        int e = lane + 32*it;
        if (it < 10 || e < 324)
            Vv[(e/18)*19 + (e%18)] = (e/18 == e%18) ? 1.f : 0.f;
    }
    // V item indices (162 items over 6 iterations) — round-invariant
    int piv[6], kkV[6];
    #pragma unroll
    for (int it = 0; it < 6; it++) {
        int t = lane + 32*it;
        if (t > 161) t = 161;                 // clamped lanes never store
        piv[it] = t / 18;
        kkV[it] = (t % 18) * 19;
    }
    const bool vva5 = (lane + 160) < 162;
    // A block indices (81 blocks over 3 iterations) — round-invariant
    int bi[3], bj[3];
    #pragma unroll
    for (int it = 0; it < 3; it++) {
        int bb = lane + 32*it;
        if (bb > 80) bb = 80;                 // clamped lanes never store
        bi[it] = bb / 9;
        bj[it] = bb % 9;
    }
    const bool ba2 = (lane + 64) < 81;
    __syncwarp();

    for (int sw = 0; sw < nsweep; sw++) {
        for (int r = 0; r < 17; r++) {
            // pivot: lane i (i<9) owns pair i of this round (regs, no smem)
            float c_ = 1.f, s_ = 0.f; int ppq_ = 0;
            if (lane < 9) {
                int a   = (lane == 0) ? 0 : (1 + ((lane - 1 + r) % 17));
                int jj  = 17 - lane;
                int bb2 = 1 + ((jj - 1 + r) % 17);
                int p = a < bb2 ? a : bb2;
                int q = a < bb2 ? bb2 : a;
                float app = A[p*19 + p], aqq = A[q*19 + q], apq = A[p*19 + q];
                if (fabsf(apq) > 1e-36f) {
                    float tau = (aqq - app) / (2.f * apq);
                    float tt  = 1.f / (fabsf(tau) + sqrtf(1.f + tau*tau));
                    if (tau < 0.f) tt = -tt;
                    c_ = rsqrtf(1.f + tt*tt);
                    s_ = tt * c_;
                }
                ppq_ = (p << 5) | q;
            }
            __syncwarp();   // pivot reads of A complete before block writes
            // fused A block updates: B' = Ri^T B Rj  (blocks fully disjoint)
            #pragma unroll
            for (int it = 0; it < 3; it++) {
                int i = bi[it], j = bj[it];
                int   pqI = __shfl_sync(0xffffffffu, ppq_, i);
                int   pqJ = __shfl_sync(0xffffffffu, ppq_, j);
                float ci  = __shfl_sync(0xffffffffu, c_, i);
                float si  = __shfl_sync(0xffffffffu, s_, i);
                float cj  = __shfl_sync(0xffffffffu, c_, j);
                float sj  = __shfl_sync(0xffffffffu, s_, j);
                if (it == 2 && !ba2) continue;
                int pI = pqI >> 5, qI = pqI & 31;
                int pJ = pqJ >> 5, qJ = pqJ & 31;
                float* Ap = &A[pI*19]; float* Aq = &A[qI*19];
                float b00 = Ap[pJ], b01 = Ap[qJ];
                float b10 = Aq[pJ], b11 = Aq[qJ];
                float t00 = ci*b00 - si*b10, t01 = ci*b01 - si*b11;
                float t10 = si*b00 + ci*b10, t11 = si*b01 + ci*b11;
                Ap[pJ] = cj*t00 - sj*t01;
                Ap[qJ] = sj*t00 + cj*t01;
                Aq[pJ] = cj*t10 - sj*t11;
                Aq[qJ] = sj*t10 + cj*t11;
            }
            // V column rotations (V J)
            #pragma unroll
            for (int it = 0; it < 6; it++) {
                int pi2 = piv[it];
                int   pq = __shfl_sync(0xffffffffu, ppq_, pi2);
                float ci = __shfl_sync(0xffffffffu, c_, pi2);
                float si = __shfl_sync(0xffffffffu, s_, pi2);
                if (it == 5 && !vva5) continue;
                int p = pq >> 5, q = pq & 31;
                float* Vk = &Vv[kkV[it]];
                float vkp = Vk[p], vkq = Vk[q];
                Vk[p] = ci*vkp - si*vkq;
                Vk[q] = si*vkp + ci*vkq;
            }
            __syncwarp();   // writes visible to next round's pivot
        }
    }
}

// --------------------------------------- eigh + log for all Q/K/V matrices
#define EW 768
__global__ __launch_bounds__(256) void k_eighlog() {
    __shared__ float sm[8*EW];
    int wid = threadIdx.x >> 5, lane = threadIdx.x & 31;
    size_t mat = (size_t)blockIdx.x * 8 + wid;
    float* A  = &sm[wid*EW];
    float* Vv = A + 342;
    float* ev = Vv + 342;
    float* src = &g_spd[mat * 324];
    for (int e = lane; e < 324; e += 32) A[(e/18)*19 + (e%18)] = src[e];
    __syncwarp();
    warp_jacobi18(A, Vv, lane, NSWEEP);
    for (int k = lane; k < 18; k += 32) ev[k] = logf(fmaxf(A[k*19 + k], 1e-38f));
    __syncwarp();
    // pre-scale: A[i][k] = Vv[i][k] * ev[k]  (A dead; single FFMA per k below)
    for (int e = lane; e < 324; e += 32) {
        int i = e / 18, k = e % 18;
        A[i*19 + k] = Vv[i*19 + k] * ev[k];
    }
    __syncwarp();
    // log-matrix is symmetric: compute 171 triu elements, mirror the store
    for (int t = lane; t < 171; t += 32) {
        int i = 0, rem = t;
        while (rem >= 18 - i) { rem -= 18 - i; i++; }
        int j = i + rem;
        float s = 0.f;
        #pragma unroll
        for (int k = 0; k < 18; k++) s += A[i*19 + k] * Vv[j*19 + k];
        src[i*18 + j] = s;
        if (i != j) src[j*18 + i] = s;
    }
}

// ------------- attention mix: energies, softmax, mix -> write into Q slots
__global__ __launch_bounds__(288) void k_attn_mix() {
    __shared__ float sLQ[3*324], sLK[3*324], sLV[3*324];
    __shared__ float sE[9], sP[9];
    int b = blockIdx.x, tid = threadIdx.x;
    int warp = tid >> 5, lane = tid & 31;
    size_t base = (size_t)b * 9 * 324;
    for (int t = tid; t < 3*324; t += 288) {
        int mm = t / 324, e = t % 324;
        sLQ[t] = g_spd[base + (mm*3 + 0)*324 + e];
        sLK[t] = g_spd[base + (mm*3 + 1)*324 + e];
        sLV[t] = g_spd[base + (mm*3 + 2)*324 + e];
    }
    __syncthreads();
    {   // 9 warps -> 9 (i,j) energy pairs
        int i = warp / 3, j = warp % 3;
        float s = 0.f;
        for (int e = lane; e < 324; e += 32) {
            float d = sLQ[i*324 + e] - sLK[j*324 + e];
            s += d*d;
        }
        #pragma unroll
        for (int d = 16; d; d >>= 1) s += __shfl_xor_sync(0xffffffffu, s, d);
        if (!lane) sE[i*3 + j] = s;
    }
    __syncthreads();
    if (tid < 3) {
        float sc[3]; float mx = -1e30f;
        #pragma unroll
        for (int j = 0; j < 3; j++) {
            sc[j] = 1.f / (1.f + log1pf(sE[tid*3 + j]));
            mx = fmaxf(mx, sc[j]);
        }
        float ss = 0.f;
        #pragma unroll
        for (int j = 0; j < 3; j++) { sc[j] = expf(sc[j] - mx); ss += sc[j]; }
        #pragma unroll
        for (int j = 0; j < 3; j++) sP[tid*3 + j] = sc[j] / ss;
    }
    __syncthreads();
    // mixed[j] = sum_i P[j,i] logV[i]  -> overwrite the (dead) logQ slot (j*3+0)
    for (int t = tid; t < 3*324; t += 288) {
        int j = t / 324, e = t % 324;
        float v = sP[j*3+0]*sLV[e] + sP[j*3+1]*sLV[324+e] + sP[j*3+2]*sLV[648+e];
        g_spd[base + (j*3 + 0)*324 + e] = v;
    }
}

// ------------- eigh(mixed) + rect-log + triu-vec (full 8-warp occupancy)
// identity: log(spd_rect(spd_exp(M), eps)) = U diag(max(s, log(eps))) U^T
__global__ __launch_bounds__(256) void k_eighfin() {
    __shared__ float sm[8*EW];
    int wid = threadIdx.x >> 5, lane = threadIdx.x & 31;
    int mat = blockIdx.x * 8 + wid;       // 0..6143: (b,m)
    int b = mat / 3, m = mat % 3;
    float* A  = &sm[wid*EW];
    float* Vv = A + 342;
    float* ev = Vv + 342;
    const float* src = &g_spd[((size_t)b*9 + m*3 + 0)*324];
    for (int e = lane; e < 324; e += 32) A[(e/18)*19 + (e%18)] = src[e];
    __syncwarp();
    warp_jacobi18(A, Vv, lane, NSWEEP);
    for (int k = lane; k < 18; k += 32) ev[k] = fmaxf(A[k*19 + k], LN_RECT);
    __syncwarp();
    for (int e = lane; e < 324; e += 32) {
        int i = e / 18, k = e % 18;
        A[i*19 + k] = Vv[i*19 + k] * ev[k];
    }
    __syncwarp();
    for (int t = lane; t < 171; t += 32) {
        int i = 0, rem = t;
        while (rem >= 18 - i) { rem -= 18 - i; i++; }
        int j = i + rem;
        float s = 0.f;
        #pragma unroll
        for (int k = 0; k < 18; k++) s += A[i*19 + k] * Vv[j*19 + k];
        g_vec[(size_t)b*VECLEN + m*171 + t] = s;
    }
}

// ------------------------------------------------------------- output head
__global__ void k_out(const float* __restrict__ Wl, const float* __restrict__ bl,
                      float* __restrict__ out) {
    int g = blockIdx.x * blockDim.x + threadIdx.x;
    if (g >= BS*4) return;
    int b = g >> 2, j = g & 3;
    float s = bl[j];
    const float* v = &g_vec[(size_t)b*VECLEN];
    for (int t = 0; t < VECLEN; t++) s += v[t] * Wl[t*4 + j];
    out[g] = s;
}

// ---------------------------------------------------------------------------
extern "C" void kernel_launch(void* const* d_in, const int* in_sizes, int n_in,
                              void* d_out, int out_size) {
    const float* x   = (const float*)d_in[0];
    const float* W1  = (const float*)d_in[1];
    const float* b1  = (const float*)d_in[2];
    const float* g1  = (const float*)d_in[3];
    const float* be1 = (const float*)d_in[4];
    const float* W2  = (const float*)d_in[5];
    const float* b2  = (const float*)d_in[6];
    const float* g2  = (const float*)d_in[7];
    const float* be2 = (const float*)d_in[8];
    const float* Wq  = (const float*)d_in[9];
    const float* Wk  = (const float*)d_in[10];
    const float* Wv  = (const float*)d_in[11];
    const float* Wl  = (const float*)d_in[12];
    const float* bl  = (const float*)d_in[13];
    float* out = (float*)d_out;

    k_zero<<<1, 128>>>();
    k_conv1<<<(BS*WIN + 255)/256, 256>>>(x, W1, b1);
    k_fin1<<<1, 32>>>(g1, be1);
    k_conv2<<<dim3((W2L + CTILE - 1)/CTILE, BS), 256>>>(W2, b2);
    k_fin2<<<1, 32>>>(g2, be2);
    k_cov<<<dim3(NEP, BS), 192>>>(Wq, Wk, Wv);
    k_eighlog<<<NMATQKV/8, 256>>>();
    k_attn_mix<<<BS, 288>>>();
    k_eighfin<<<(BS*NEP)/8, 256>>>();
    k_out<<<(BS*4 + 255)/256, 256>>>(Wl, bl, out);
}

// round 17
// speedup vs baseline: 3.5963x; 1.0215x over previous
#include <cuda_runtime.h>
#include <math.h>

#define BS    2048
#define C1    22
#define WIN   438
#define C2    20
#define W2L   439
#define NIN   20
#define NOUT  18
#define NEP   3
#define KW    12
#define NMATQKV (BS*NEP*3)      // 18432 matrices (Q,K,V per (b,m))
#define VECLEN  513             // 3 * 171
#define LN_RECT (-9.2103403719761836f)  // log(1e-4)
#define NSWEEP  4

// ---------------- scratch (static device globals; no cudaMalloc allowed) ----
__device__ float g_h1[BS*C1*WIN];          // conv1 raw output
__device__ float g_h2[BS*C2*W2L];          // conv2 raw output
__device__ float g_spd[(size_t)NMATQKV*NOUT*NOUT];  // Q/K/V -> logm; Q slot reused for mixed
__device__ float g_vec[(size_t)BS*VECLEN];
__device__ float g_red[2*C1 + 2*C2];       // s1[22] q1[22] s2[20] q2[20]
__device__ float g_aff[2*C1 + 2*C2];       // a1[22] c1[22] a2[20] c2[20]

// ---------------------------------------------------------------- zero stats
__global__ void k_zero() {
    int t = threadIdx.x;
    if (t < 2*C1 + 2*C2) g_red[t] = 0.f;
}

// ------------------------------------------------------- conv1 + bn1 stats
__global__ void k_conv1(const float* __restrict__ x,
                        const float* __restrict__ W1,
                        const float* __restrict__ b1) {
    __shared__ float w1s[C1*C1];
    __shared__ float sS[C1], sQ[C1];
    int tid = threadIdx.x;
    for (int t = tid; t < C1*C1; t += blockDim.x) w1s[t] = W1[t];  // W1[o,0,h,0]
    if (tid < C1) { sS[tid] = 0.f; sQ[tid] = 0.f; }
    __syncthreads();

    int g = blockIdx.x * blockDim.x + tid;
    bool valid = (g < BS*WIN);
    int b = g / WIN, w = g % WIN;
    float xv[C1];
    if (valid) {
        #pragma unroll
        for (int h = 0; h < C1; h++) xv[h] = x[((size_t)b*C1 + h)*WIN + w];
    }
    for (int o = 0; o < C1; o++) {
        float acc = 0.f;
        if (valid) {
            acc = b1[o];
            #pragma unroll
            for (int h = 0; h < C1; h++) acc += xv[h] * w1s[o*C1 + h];
            g_h1[((size_t)b*C1 + o)*WIN + w] = acc;
        }
        float s = acc, q = acc*acc;
        #pragma unroll
        for (int d = 16; d; d >>= 1) {
            s += __shfl_xor_sync(0xffffffffu, s, d);
            q += __shfl_xor_sync(0xffffffffu, q, d);
        }
        if ((tid & 31) == 0) { atomicAdd(&sS[o], s); atomicAdd(&sQ[o], q); }
    }
    __syncthreads();
    if (tid < C1) {
        atomicAdd(&g_red[tid], sS[tid]);
        atomicAdd(&g_red[C1 + tid], sQ[tid]);
    }
}

__global__ void k_fin1(const float* __restrict__ g1, const float* __restrict__ be1) {
    int c = threadIdx.x;
    if (c >= C1) return;
    float cnt  = (float)((size_t)BS*WIN);
    float mean = g_red[c] / cnt;
    float var  = g_red[C1 + c] / cnt - mean*mean;
    float a = g1[c] * rsqrtf(var + 1e-5f);
    g_aff[c]      = a;
    g_aff[C1 + c] = be1[c] - mean*a;
}

// ------------------------------------------------------- conv2 + bn2 stats
#define CTILE 256
#define TPAD  268   // 256 + 12; rows 16B-aligned (268*4=1072=67*16) for float4
__global__ __launch_bounds__(256) void k_conv2(const float* __restrict__ W2,
                                               const float* __restrict__ b2) {
    __shared__ __align__(16) float tile[C1*TPAD];   // 5896 floats
    __shared__ __align__(16) float w2s[C2*C1*KW];   // 5280 floats
    __shared__ float sS[C2], sQ[C2];
    int tid = threadIdx.x;
    int b  = blockIdx.y;
    int w0 = blockIdx.x * CTILE;

    for (int t = tid; t < C2*C1*KW; t += 256) w2s[t] = W2[t];
    if (tid < C2) { sS[tid] = 0.f; sQ[tid] = 0.f; }
    for (int t = tid; t < C1*TPAD; t += 256) {
        int i = t / TPAD, dw = t % TPAD;
        int gw = w0 - 6 + dw;
        float v = 0.f;
        if (gw >= 0 && gw < WIN)
            v = g_aff[i] * g_h1[((size_t)b*C1 + i)*WIN + gw] + g_aff[C1 + i];
        tile[t] = v;
    }
    __syncthreads();

    int o_grp = tid >> 6;        // 0..3 (warp-uniform)
    int widx  = tid & 63;
    int wl0   = widx * 4;

    float acc[20];
    #pragma unroll
    for (int oi = 0; oi < 5; oi++) {
        float bb = b2[o_grp*5 + oi];
        #pragma unroll
        for (int wj = 0; wj < 4; wj++) acc[oi*4 + wj] = bb;
    }
    for (int i = 0; i < C1; i++) {
        // 16 floats via 4 LDS.128 (conflict-free: 16B lane stride), use 15
        float4 t0 = *(const float4*)&tile[i*TPAD + wl0];
        float4 t1 = *(const float4*)&tile[i*TPAD + wl0 + 4];
        float4 t2 = *(const float4*)&tile[i*TPAD + wl0 + 8];
        float4 t3 = *(const float4*)&tile[i*TPAD + wl0 + 12];
        float tv[15] = {t0.x, t0.y, t0.z, t0.w,
                        t1.x, t1.y, t1.z, t1.w,
                        t2.x, t2.y, t2.z, t2.w,
                        t3.x, t3.y, t3.z};
        #pragma unroll
        for (int oi = 0; oi < 5; oi++) {
            int o = o_grp*5 + oi;
            // 12 contiguous weights via 3 uniform LDS.128
            const float4* wp = (const float4*)&w2s[(o*C1 + i)*KW];
            float4 wa = wp[0], wb = wp[1], wc = wp[2];
            float wk[12] = {wa.x, wa.y, wa.z, wa.w,
                            wb.x, wb.y, wb.z, wb.w,
                            wc.x, wc.y, wc.z, wc.w};
            #pragma unroll
            for (int k = 0; k < KW; k++) {
                float wv = wk[k];
                #pragma unroll
                for (int wj = 0; wj < 4; wj++) acc[oi*4 + wj] += tv[wj + k] * wv;
            }
        }
    }
    for (int oi = 0; oi < 5; oi++) {
        int o = o_grp*5 + oi;
        float s = 0.f, q = 0.f;
        #pragma unroll
        for (int wj = 0; wj < 4; wj++) {
            int w = w0 + wl0 + wj;
            if (w < W2L) {
                float v = acc[oi*4 + wj];
                g_h2[((size_t)b*C2 + o)*W2L + w] = v;
                s += v; q += v*v;
            }
        }
        #pragma unroll
        for (int d = 16; d; d >>= 1) {
            s += __shfl_xor_sync(0xffffffffu, s, d);
            q += __shfl_xor_sync(0xffffffffu, q, d);
        }
        if ((tid & 31) == 0) { atomicAdd(&sS[o], s); atomicAdd(&sQ[o], q); }
    }
    __syncthreads();
    if (tid < C2) {
        atomicAdd(&g_red[2*C1 + tid], sS[tid]);
        atomicAdd(&g_red[2*C1 + C2 + tid], sQ[tid]);
    }
}

__global__ void k_fin2(const float* __restrict__ g2, const float* __restrict__ be2) {
    int c = threadIdx.x;
    if (c >= C2) return;
    float cnt  = (float)((size_t)BS*W2L);
    float mean = g_red[2*C1 + c] / cnt;
    float var  = g_red[2*C1 + C2 + c] / cnt - mean*mean;
    float a = g2[c] * rsqrtf(var + 1e-5f);
    g_aff[2*C1 + c]      = a;
    g_aff[2*C1 + C2 + c] = be2[c] - mean*a;
}

// ----------------------------------------- covariance + Q/K/V congruence
#define SP 149   // row stride for sig (gcd(149,32)=1)
__global__ __launch_bounds__(192) void k_cov(const float* __restrict__ Wq,
                                             const float* __restrict__ Wk,
                                             const float* __restrict__ Wv) {
    __shared__ float sig[C2*SP];
    __shared__ float Cm[C2*C2];
    __shared__ float T[C2*NOUT];
    __shared__ float Ws[C2*NOUT];
    __shared__ float mean_s[C2];
    __shared__ float trs;
    const int offs[NEP] = {0, 147, 293};
    const int Ls[NEP]   = {147, 146, 146};
    int m = blockIdx.x, b = blockIdx.y;
    int off = offs[m], L = Ls[m];
    int tid = threadIdx.x;
    int warp = tid >> 5, lane = tid & 31;

    for (int t = tid; t < C2*L; t += 192) {
        int c = t / L, l = t % L;
        sig[c*SP + l] = g_aff[2*C1 + c] * g_h2[((size_t)b*C2 + c)*W2L + off + l]
                      + g_aff[2*C1 + C2 + c];
    }
    __syncthreads();
    for (int r = warp; r < C2; r += 6) {
        float s = 0.f;
        for (int l = lane; l < L; l += 32) s += sig[r*SP + l];
        #pragma unroll
        for (int d = 16; d; d >>= 1) s += __shfl_xor_sync(0xffffffffu, s, d);
        if (!lane) mean_s[r] = s / (float)L;
    }
    __syncthreads();
    for (int t = tid; t < C2*L; t += 192) sig[(t/L)*SP + (t%L)] -= mean_s[t/L];
    __syncthreads();
    for (int t = tid; t < 210; t += 192) {
        int p = 0, rem = t;
        while (rem >= C2 - p) { rem -= C2 - p; p++; }
        int q = p + rem;
        float s = 0.f;
        for (int l = 0; l < L; l++) s += sig[p*SP + l] * sig[q*SP + l];
        Cm[p*C2 + q] = s;
        Cm[q*C2 + p] = s;
    }
    __syncthreads();
    if (tid == 0) {
        float tr = 0.f;
        for (int i = 0; i < C2; i++) tr += Cm[i*C2 + i];
        trs = 1.f / tr;                    // (L-1) cancels in trace-normalization
    }
    __syncthreads();
    for (int t = tid; t < C2*C2; t += 192) {
        float v = Cm[t] * trs;
        if (t / C2 == t % C2) v += 1e-5f;
        Cm[t] = v;
    }
    __syncthreads();
    const float* Wp[3] = {Wq, Wk, Wv};
    for (int which = 0; which < 3; which++) {
        for (int t = tid; t < C2*NOUT; t += 192) Ws[t] = Wp[which][t];
        __syncthreads();
        for (int t = tid; t < C2*NOUT; t += 192) {
            int p = t / NOUT, j = t % NOUT;
            float s = 0.f;
            #pragma unroll
            for (int q = 0; q < C2; q++) s += Cm[p*C2 + q] * Ws[q*NOUT + j];
            T[t] = s;
        }
        __syncthreads();
        float* dst = &g_spd[((size_t)(b*NEP + m)*3 + which)*NOUT*NOUT];
        for (int t = tid; t < NOUT*NOUT; t += 192) {
            int i = t / NOUT, j = t % NOUT;
            float s = 0.f;
            #pragma unroll
            for (int p = 0; p < C2; p++) s += Ws[p*NOUT + i] * T[p*NOUT + j];
            dst[t] = s;
        }
        __syncthreads();
    }
}

// ------------------------------ warp-level parallel-round Jacobi (18x18)
// A, Vv: 18x18 in smem with row stride 19.
// v3: SYMMETRIC fused block update. A stays symmetric every round, so block
// (j,i) is exactly the transpose of block (i,j). Process only the 45
// canonical blocks (i<=j); write result naturally AND transpose-mirrored.
// Mirror targets are non-canonical blocks (never read/canonically written)
// -> no hazards; diagonal blocks self-mirror (same-lane same-addr rewrite).
__device__ __forceinline__ void warp_jacobi18(float* A, float* Vv,
                                              int lane, int nsweep) {
    #pragma unroll
    for (int it = 0; it < 11; it++) {
        int e = lane + 32*it;
        if (it < 10 || e < 324)
            Vv[(e/18)*19 + (e%18)] = (e/18 == e%18) ? 1.f : 0.f;
    }
    // V item indices (162 items over 6 iterations) — round-invariant
    int piv[6], kkV[6];
    #pragma unroll
    for (int it = 0; it < 6; it++) {
        int t = lane + 32*it;
        if (t > 161) t = 161;                 // clamped lanes never store
        piv[it] = t / 18;
        kkV[it] = (t % 18) * 19;
    }
    const bool vva5 = (lane + 160) < 162;
    // canonical A block indices (45 blocks i<=j over 2 iterations)
    int bi[2], bj[2];
    #pragma unroll
    for (int it = 0; it < 2; it++) {
        int bb = lane + 32*it;
        if (bb > 44) bb = 44;                 // clamped lanes never store
        int i = 0, rem = bb;
        while (rem >= 9 - i) { rem -= 9 - i; i++; }
        bi[it] = i;
        bj[it] = i + rem;
    }
    const bool ba1 = (lane + 32) < 45;
    __syncwarp();

    for (int sw = 0; sw < nsweep; sw++) {
        for (int r = 0; r < 17; r++) {
            // pivot: lane i (i<9) owns pair i of this round (regs, no smem)
            float c_ = 1.f, s_ = 0.f; int ppq_ = 0;
            if (lane < 9) {
                int a   = (lane == 0) ? 0 : (1 + ((lane - 1 + r) % 17));
                int jj  = 17 - lane;
                int bb2 = 1 + ((jj - 1 + r) % 17);
                int p = a < bb2 ? a : bb2;
                int q = a < bb2 ? bb2 : a;
                float app = A[p*19 + p], aqq = A[q*19 + q], apq = A[p*19 + q];
                if (fabsf(apq) > 1e-36f) {
                    float tau = (aqq - app) / (2.f * apq);
                    float tt  = 1.f / (fabsf(tau) + sqrtf(1.f + tau*tau));
                    if (tau < 0.f) tt = -tt;
                    c_ = rsqrtf(1.f + tt*tt);
                    s_ = tt * c_;
                }
                ppq_ = (p << 5) | q;
            }
            __syncwarp();   // pivot reads of A complete before block writes
            // fused canonical block updates: B' = Ri^T B Rj, mirror-stored
            #pragma unroll
            for (int it = 0; it < 2; it++) {
                int i = bi[it], j = bj[it];
                int   pqI = __shfl_sync(0xffffffffu, ppq_, i);
                int   pqJ = __shfl_sync(0xffffffffu, ppq_, j);
                float ci  = __shfl_sync(0xffffffffu, c_, i);
                float si  = __shfl_sync(0xffffffffu, s_, i);
                float cj  = __shfl_sync(0xffffffffu, c_, j);
                float sj  = __shfl_sync(0xffffffffu, s_, j);
                if (it == 1 && !ba1) continue;
                int pI = pqI >> 5, qI = pqI & 31;
                int pJ = pqJ >> 5, qJ = pqJ & 31;
                float* Ap = &A[pI*19]; float* Aq = &A[qI*19];
                float b00 = Ap[pJ], b01 = Ap[qJ];
                float b10 = Aq[pJ], b11 = Aq[qJ];
                float t00 = ci*b00 - si*b10, t01 = ci*b01 - si*b11;
                float t10 = si*b00 + ci*b10, t11 = si*b01 + ci*b11;
                float n00 = cj*t00 - sj*t01;
                float n01 = sj*t00 + cj*t01;
                float n10 = cj*t10 - sj*t11;
                float n11 = sj*t10 + cj*t11;
                Ap[pJ] = n00; Ap[qJ] = n01;
                Aq[pJ] = n10; Aq[qJ] = n11;
                // transpose mirror into block (j,i)
                float* Bp = &A[pJ*19]; float* Bq = &A[qJ*19];
                Bp[pI] = n00; Bp[qI] = n10;
                Bq[pI] = n01; Bq[qI] = n11;
            }
            // V column rotations (V J)
            #pragma unroll
            for (int it = 0; it < 6; it++) {
                int pi2 = piv[it];
                int   pq = __shfl_sync(0xffffffffu, ppq_, pi2);
                float ci = __shfl_sync(0xffffffffu, c_, pi2);
                float si = __shfl_sync(0xffffffffu, s_, pi2);
                if (it == 5 && !vva5) continue;
                int p = pq >> 5, q = pq & 31;
                float* Vk = &Vv[kkV[it]];
                float vkp = Vk[p], vkq = Vk[q];
                Vk[p] = ci*vkp - si*vkq;
                Vk[q] = si*vkp + ci*vkq;
            }
            __syncwarp();   // writes visible to next round's pivot
        }
    }
}

// --------------------------------------- eigh + log for all Q/K/V matrices
#define EW 768
__global__ __launch_bounds__(256) void k_eighlog() {
    __shared__ float sm[8*EW];
    int wid = threadIdx.x >> 5, lane = threadIdx.x & 31;
    size_t mat = (size_t)blockIdx.x * 8 + wid;
    float* A  = &sm[wid*EW];
    float* Vv = A + 342;
    float* ev = Vv + 342;
    float* src = &g_spd[mat * 324];
    for (int e = lane; e < 324; e += 32) A[(e/18)*19 + (e%18)] = src[e];
    __syncwarp();
    warp_jacobi18(A, Vv, lane, NSWEEP);
    for (int k = lane; k < 18; k += 32) ev[k] = logf(fmaxf(A[k*19 + k], 1e-38f));
    __syncwarp();
    // pre-scale: A[i][k] = Vv[i][k] * ev[k]  (A dead; single FFMA per k below)
    for (int e = lane; e < 324; e += 32) {
        int i = e / 18, k = e % 18;
        A[i*19 + k] = Vv[i*19 + k] * ev[k];
    }
    __syncwarp();
    // log-matrix is symmetric: compute 171 triu elements, mirror the store
    for (int t = lane; t < 171; t += 32) {
        int i = 0, rem = t;
        while (rem >= 18 - i) { rem -= 18 - i; i++; }
        int j = i + rem;
        float s = 0.f;
        #pragma unroll
        for (int k = 0; k < 18; k++) s += A[i*19 + k] * Vv[j*19 + k];
        src[i*18 + j] = s;
        if (i != j) src[j*18 + i] = s;
    }
}

// ------------- attention mix: energies, softmax, mix -> write into Q slots
__global__ __launch_bounds__(288) void k_attn_mix() {
    __shared__ float sLQ[3*324], sLK[3*324], sLV[3*324];
    __shared__ float sE[9], sP[9];
    int b = blockIdx.x, tid = threadIdx.x;
    int warp = tid >> 5, lane = tid & 31;
    size_t base = (size_t)b * 9 * 324;
    for (int t = tid; t < 3*324; t += 288) {
        int mm = t / 324, e = t % 324;
        sLQ[t] = g_spd[base + (mm*3 + 0)*324 + e];
        sLK[t] = g_spd[base + (mm*3 + 1)*324 + e];
        sLV[t] = g_spd[base + (mm*3 + 2)*324 + e];
    }
    __syncthreads();
    {   // 9 warps -> 9 (i,j) energy pairs
        int i = warp / 3, j = warp % 3;
        float s = 0.f;
        for (int e = lane; e < 324; e += 32) {
            float d = sLQ[i*324 + e] - sLK[j*324 + e];
            s += d*d;
        }
        #pragma unroll
        for (int d = 16; d; d >>= 1) s += __shfl_xor_sync(0xffffffffu, s, d);
        if (!lane) sE[i*3 + j] = s;
    }
    __syncthreads();
    if (tid < 3) {
        float sc[3]; float mx = -1e30f;
        #pragma unroll
        for (int j = 0; j < 3; j++) {
            sc[j] = 1.f / (1.f + log1pf(sE[tid*3 + j]));
            mx = fmaxf(mx, sc[j]);
        }
        float ss = 0.f;
        #pragma unroll
        for (int j = 0; j < 3; j++) { sc[j] = expf(sc[j] - mx); ss += sc[j]; }
        #pragma unroll
        for (int j = 0; j < 3; j++) sP[tid*3 + j] = sc[j] / ss;
    }
    __syncthreads();
    // mixed[j] = sum_i P[j,i] logV[i]  -> overwrite the (dead) logQ slot (j*3+0)
    for (int t = tid; t < 3*324; t += 288) {
        int j = t / 324, e = t % 324;
        float v = sP[j*3+0]*sLV[e] + sP[j*3+1]*sLV[324+e] + sP[j*3+2]*sLV[648+e];
        g_spd[base + (j*3 + 0)*324 + e] = v;
    }
}

// ------------- eigh(mixed) + rect-log + triu-vec (full 8-warp occupancy)
// identity: log(spd_rect(spd_exp(M), eps)) = U diag(max(s, log(eps))) U^T
__global__ __launch_bounds__(256) void k_eighfin() {
    __shared__ float sm[8*EW];
    int wid = threadIdx.x >> 5, lane = threadIdx.x & 31;
    int mat = blockIdx.x * 8 + wid;       // 0..6143: (b,m)
    int b = mat / 3, m = mat % 3;
    float* A  = &sm[wid*EW];
    float* Vv = A + 342;
    float* ev = Vv + 342;
    const float* src = &g_spd[((size_t)b*9 + m*3 + 0)*324];
    for (int e = lane; e < 324; e += 32) A[(e/18)*19 + (e%18)] = src[e];
    __syncwarp();
    warp_jacobi18(A, Vv, lane, NSWEEP);
    for (int k = lane; k < 18; k += 32) ev[k] = fmaxf(A[k*19 + k], LN_RECT);
    __syncwarp();
    for (int e = lane; e < 324; e += 32) {
        int i = e / 18, k = e % 18;
        A[i*19 + k] = Vv[i*19 + k] * ev[k];
    }
    __syncwarp();
    for (int t = lane; t < 171; t += 32) {
        int i = 0, rem = t;
        while (rem >= 18 - i) { rem -= 18 - i; i++; }
        int j = i + rem;
        float s = 0.f;
        #pragma unroll
        for (int k = 0; k < 18; k++) s += A[i*19 + k] * Vv[j*19 + k];
        g_vec[(size_t)b*VECLEN + m*171 + t] = s;
    }
}

// ------------------------------------------------------------- output head
__global__ void k_out(const float* __restrict__ Wl, const float* __restrict__ bl,
                      float* __restrict__ out) {
    int g = blockIdx.x * blockDim.x + threadIdx.x;
    if (g >= BS*4) return;
    int b = g >> 2, j = g & 3;
    float s = bl[j];
    const float* v = &g_vec[(size_t)b*VECLEN];
    for (int t = 0; t < VECLEN; t++) s += v[t] * Wl[t*4 + j];
    out[g] = s;
}

// ---------------------------------------------------------------------------
extern "C" void kernel_launch(void* const* d_in, const int* in_sizes, int n_in,
                              void* d_out, int out_size) {
    const float* x   = (const float*)d_in[0];
    const float* W1  = (const float*)d_in[1];
    const float* b1  = (const float*)d_in[2];
    const float* g1  = (const float*)d_in[3];
    const float* be1 = (const float*)d_in[4];
    const float* W2  = (const float*)d_in[5];
    const float* b2  = (const float*)d_in[6];
    const float* g2  = (const float*)d_in[7];
    const float* be2 = (const float*)d_in[8];
    const float* Wq  = (const float*)d_in[9];
    const float* Wk  = (const float*)d_in[10];
    const float* Wv  = (const float*)d_in[11];
    const float* Wl  = (const float*)d_in[12];
    const float* bl  = (const float*)d_in[13];
    float* out = (float*)d_out;

    k_zero<<<1, 128>>>();
    k_conv1<<<(BS*WIN + 255)/256, 256>>>(x, W1, b1);
    k_fin1<<<1, 32>>>(g1, be1);
    k_conv2<<<dim3((W2L + CTILE - 1)/CTILE, BS), 256>>>(W2, b2);
    k_fin2<<<1, 32>>>(g2, be2);
    k_cov<<<dim3(NEP, BS), 192>>>(Wq, Wk, Wv);
    k_eighlog<<<NMATQKV/8, 256>>>();
    k_attn_mix<<<BS, 288>>>();
    k_eighfin<<<(BS*NEP)/8, 256>>>();
    k_out<<<(BS*4 + 255)/256, 256>>>(Wl, bl, out);
}